// round 1
// baseline (speedup 1.0000x reference)
#include <cuda_runtime.h>
#include <math.h>

// ---------------- problem constants ----------------
#define BB   2
#define QL   1024
#define KL   4096
#define HID  2048
#define HH   16
#define HD   128
#define RD   64
#define GG   4
#define QLR  512
#define LAT  256

#define BQL  (BB*QL)   // 2048 query tokens
#define BKL  (BB*KL)   // 8192 kv tokens

// ---------------- scratch (device globals; no allocation allowed) ----------------
__device__ float g_qlat[BQL * QLR];              // 2048 x 512
__device__ float g_q   [BQL * (HH*(HD+RD))];     // 2048 x 3072
__device__ float g_ckv [BKL * (GG*LAT)];         // 8192 x 1024
__device__ float g_kv  [BKL * (HH*2*HD)];        // 8192 x 4096 (128 MB)
__device__ float g_attn[BQL * (HH*HD)];          // 2048 x 2048

// =================================================================
// Generic tiled SGEMM: C[M,N] = A[M,K] * B[K,N]
// Tile 64x64, BK=16, 256 threads, 4x4 per-thread microtile.
// M,N implied by grid (must divide 64); K must divide 16.
// blockIdx.z batching via element strides sAz/sBz/sCz.
// =================================================================
__global__ void sgemm_kernel(const float* __restrict__ A,
                             const float* __restrict__ B,
                             float* __restrict__ C,
                             int K, int lda, int ldb, int ldc,
                             long long sAz, long long sBz, long long sCz)
{
    A += (long long)blockIdx.z * sAz;
    B += (long long)blockIdx.z * sBz;
    C += (long long)blockIdx.z * sCz;

    __shared__ float As[16][68];   // [k][m], padded
    __shared__ float Bs[16][64];   // [k][n]

    const int tid = threadIdx.x;
    const int m0 = blockIdx.y * 64;
    const int n0 = blockIdx.x * 64;

    const int tr = tid >> 4;      // 0..15 -> m rows 4*tr..
    const int tc = tid & 15;      // 0..15 -> n cols 4*tc..

    const int arow = tid >> 2, a4 = tid & 3;    // A loader: row, k-quarter
    const int brow = tid >> 4, b4 = tid & 15;   // B loader: k-row, n-quarter

    float acc[4][4];
#pragma unroll
    for (int i = 0; i < 4; i++)
#pragma unroll
        for (int j = 0; j < 4; j++) acc[i][j] = 0.f;

    const float* Aptr = A + (long long)(m0 + arow) * lda + a4 * 4;
    const float* Bptr = B + (long long)brow * ldb + n0 + b4 * 4;

    for (int kk = 0; kk < K; kk += 16) {
        float4 av = *(const float4*)(Aptr + kk);
        float4 bv = *(const float4*)(Bptr + (long long)kk * ldb);
        As[a4 * 4 + 0][arow] = av.x;
        As[a4 * 4 + 1][arow] = av.y;
        As[a4 * 4 + 2][arow] = av.z;
        As[a4 * 4 + 3][arow] = av.w;
        *(float4*)&Bs[brow][b4 * 4] = bv;
        __syncthreads();

#pragma unroll
        for (int k = 0; k < 16; k++) {
            float4 a = *(const float4*)&As[k][tr * 4];
            float4 b = *(const float4*)&Bs[k][tc * 4];
            acc[0][0] += a.x * b.x; acc[0][1] += a.x * b.y; acc[0][2] += a.x * b.z; acc[0][3] += a.x * b.w;
            acc[1][0] += a.y * b.x; acc[1][1] += a.y * b.y; acc[1][2] += a.y * b.z; acc[1][3] += a.y * b.w;
            acc[2][0] += a.z * b.x; acc[2][1] += a.z * b.y; acc[2][2] += a.z * b.z; acc[2][3] += a.z * b.w;
            acc[3][0] += a.w * b.x; acc[3][1] += a.w * b.y; acc[3][2] += a.w * b.z; acc[3][3] += a.w * b.w;
        }
        __syncthreads();
    }

#pragma unroll
    for (int i = 0; i < 4; i++) {
        float4 v = make_float4(acc[i][0], acc[i][1], acc[i][2], acc[i][3]);
        *(float4*)&C[(long long)(m0 + tr * 4 + i) * ldc + n0 + tc * 4] = v;
    }
}

// =================================================================
// RMSNorm over segments: grid.x = row, grid.y = seg. 256 threads.
// x[row*rowStride + seg*segStride + i], w[seg*segStride + i], i < n
// =================================================================
__global__ void rmsnorm_kernel(float* __restrict__ x, const float* __restrict__ w,
                               int n, int rowStride, int segStride)
{
    float* p = x + (long long)blockIdx.x * rowStride + (long long)blockIdx.y * segStride;
    const float* wp = w + (long long)blockIdx.y * segStride;

    __shared__ float red[8];
    __shared__ float rs;

    float s = 0.f;
    for (int i = threadIdx.x; i < n; i += 256) { float v = p[i]; s += v * v; }
#pragma unroll
    for (int o = 16; o; o >>= 1) s += __shfl_xor_sync(0xffffffffu, s, o);
    if ((threadIdx.x & 31) == 0) red[threadIdx.x >> 5] = s;
    __syncthreads();
    if (threadIdx.x == 0) {
        float t = 0.f;
#pragma unroll
        for (int i = 0; i < 8; i++) t += red[i];
        rs = rsqrtf(t / (float)n + 1e-6f);
    }
    __syncthreads();
    float r = rs;
    for (int i = threadIdx.x; i < n; i += 256) p[i] = p[i] * r * wp[i];
}

// =================================================================
// Flash attention, fp32. BM=64, BN=64, D=128. 256 threads.
// Q: g_q rows (b*QL+q), stride 3072, head off h*192, d<128
// K: g_kv rows (b*KL+s), stride 4096, off h*256
// V: g_kv same rows, off h*256+128
// O: g_attn rows (b*QL+q), stride 2048, off h*128
// smem: Qs[64][132] | union(KT[128][68], Vs[64][132]) | Ss[64][65] | m/l/alpha[64]
// =================================================================
#define FA_SMEM ((64*132 + 128*68 + 64*65 + 3*64) * 4)

__global__ void flash_kernel(const float* __restrict__ Qg,
                             const float* __restrict__ KVg,
                             float* __restrict__ Og)
{
    extern __shared__ float sm[];
    float* Qs  = sm;                       // [64][132]
    float* KT  = sm + 64 * 132;            // [128][68]  (K^T)
    float* Vs  = KT;                       // [64][132]  (reuses K buffer)
    float* Ss  = sm + 64 * 132 + 128 * 68; // [64][65]
    float* m_s = Ss + 64 * 65;
    float* l_s = m_s + 64;
    float* a_s = l_s + 64;

    const int tid = threadIdx.x;
    const int qt = blockIdx.x, h = blockIdx.y, b = blockIdx.z;
    const float scale = 0.08838834764831845f;   // 1/sqrt(128)

    // load Q tile
    {
        int r = tid >> 2, c4 = tid & 3;
        const float* src = Qg + (long long)(b * QL + qt * 64 + r) * 3072 + h * 192;
#pragma unroll
        for (int j = 0; j < 8; j++) {
            float4 v = *(const float4*)(src + (c4 + 4 * j) * 4);
            *(float4*)&Qs[r * 132 + (c4 + 4 * j) * 4] = v;
        }
    }
    if (tid < 64) { m_s[tid] = -1e30f; l_s[tid] = 0.f; }

    const int tr = tid >> 4, tc = tid & 15;   // S microtile map
    const int rp = 4 * (tid >> 4);            // PV rows
    const int dc = (tid & 15) * 8;            // PV d-cols

    float o[4][8];
#pragma unroll
    for (int i = 0; i < 4; i++)
#pragma unroll
        for (int j = 0; j < 8; j++) o[i][j] = 0.f;

    for (int jb = 0; jb < KL / 64; jb++) {
        // ---- load K transposed into KT[d][c] ----
        {
            int c = tid >> 2, d4g = tid & 3;
            const float* src = KVg + (long long)(b * KL + jb * 64 + c) * 4096 + h * 256;
#pragma unroll
            for (int j = 0; j < 8; j++) {
                int d4 = d4g + 4 * j;
                float4 v = *(const float4*)(src + d4 * 4);
                KT[(d4 * 4 + 0) * 68 + c] = v.x;
                KT[(d4 * 4 + 1) * 68 + c] = v.y;
                KT[(d4 * 4 + 2) * 68 + c] = v.z;
                KT[(d4 * 4 + 3) * 68 + c] = v.w;
            }
        }
        __syncthreads();

        // ---- S = scale * Q K^T (each thread 4x4) ----
        float acc[4][4];
#pragma unroll
        for (int i = 0; i < 4; i++)
#pragma unroll
            for (int j = 0; j < 4; j++) acc[i][j] = 0.f;

#pragma unroll 4
        for (int d4 = 0; d4 < 32; d4++) {
            float4 qv[4];
#pragma unroll
            for (int i = 0; i < 4; i++)
                qv[i] = *(const float4*)&Qs[(4 * tr + i) * 132 + d4 * 4];
#pragma unroll
            for (int dd = 0; dd < 4; dd++) {
                float4 kv4 = *(const float4*)&KT[(d4 * 4 + dd) * 68 + 4 * tc];
#pragma unroll
                for (int i = 0; i < 4; i++) {
                    float q = ((const float*)&qv[i])[dd];
                    acc[i][0] += q * kv4.x;
                    acc[i][1] += q * kv4.y;
                    acc[i][2] += q * kv4.z;
                    acc[i][3] += q * kv4.w;
                }
            }
        }
#pragma unroll
        for (int i = 0; i < 4; i++)
#pragma unroll
            for (int j = 0; j < 4; j++)
                Ss[(4 * tr + i) * 65 + 4 * tc + j] = acc[i][j] * scale;
        __syncthreads();

        // ---- online softmax row update (4 threads per row) ----
        {
            int r = tid >> 2, c0 = (tid & 3) * 16;
            float sv[16];
            float mloc = -1e30f;
#pragma unroll
            for (int j = 0; j < 16; j++) {
                sv[j] = Ss[r * 65 + c0 + j];
                mloc = fmaxf(mloc, sv[j]);
            }
            mloc = fmaxf(mloc, __shfl_xor_sync(0xffffffffu, mloc, 1));
            mloc = fmaxf(mloc, __shfl_xor_sync(0xffffffffu, mloc, 2));
            float mold = m_s[r];
            float mnew = fmaxf(mold, mloc);
            float sum = 0.f;
#pragma unroll
            for (int j = 0; j < 16; j++) {
                float pj = __expf(sv[j] - mnew);
                Ss[r * 65 + c0 + j] = pj;
                sum += pj;
            }
            sum += __shfl_xor_sync(0xffffffffu, sum, 1);
            sum += __shfl_xor_sync(0xffffffffu, sum, 2);
            if ((tid & 3) == 0) {
                float al = __expf(mold - mnew);
                a_s[r] = al;
                l_s[r] = l_s[r] * al + sum;
                m_s[r] = mnew;
            }
        }
        // ---- load V (overwrites KT buffer; K fully consumed above) ----
        {
            int r = tid >> 2, c4 = tid & 3;
            const float* src = KVg + (long long)(b * KL + jb * 64 + r) * 4096 + h * 256 + 128;
#pragma unroll
            for (int j = 0; j < 8; j++) {
                float4 v = *(const float4*)(src + (c4 + 4 * j) * 4);
                *(float4*)&Vs[r * 132 + (c4 + 4 * j) * 4] = v;
            }
        }
        __syncthreads();

        // ---- O = alpha*O + P V ----
#pragma unroll
        for (int i = 0; i < 4; i++) {
            float al = a_s[rp + i];
#pragma unroll
            for (int j = 0; j < 8; j++) o[i][j] *= al;
        }
#pragma unroll 8
        for (int k = 0; k < 64; k++) {
            float4 v0 = *(const float4*)&Vs[k * 132 + dc];
            float4 v1 = *(const float4*)&Vs[k * 132 + dc + 4];
#pragma unroll
            for (int i = 0; i < 4; i++) {
                float p = Ss[(rp + i) * 65 + k];
                o[i][0] += p * v0.x; o[i][1] += p * v0.y;
                o[i][2] += p * v0.z; o[i][3] += p * v0.w;
                o[i][4] += p * v1.x; o[i][5] += p * v1.y;
                o[i][6] += p * v1.z; o[i][7] += p * v1.w;
            }
        }
        __syncthreads();   // protect Vs/Ss for next iteration
    }

    // ---- epilogue: O /= l, write out ----
#pragma unroll
    for (int i = 0; i < 4; i++) {
        float inv = 1.f / l_s[rp + i];
        float* dst = Og + (long long)(b * QL + qt * 64 + rp + i) * 2048 + h * 128 + dc;
        float4 r0 = make_float4(o[i][0] * inv, o[i][1] * inv, o[i][2] * inv, o[i][3] * inv);
        float4 r1 = make_float4(o[i][4] * inv, o[i][5] * inv, o[i][6] * inv, o[i][7] * inv);
        *(float4*)(dst) = r0;
        *(float4*)(dst + 4) = r1;
    }
}

// =================================================================
// launch
// =================================================================
extern "C" void kernel_launch(void* const* d_in, const int* in_sizes, int n_in,
                              void* d_out, int out_size)
{
    const float* x_q       = (const float*)d_in[0];
    const float* x_kv      = (const float*)d_in[1];
    const float* W_dQ      = (const float*)d_in[2];
    const float* q_norm_w  = (const float*)d_in[3];
    const float* W_uQ      = (const float*)d_in[4];
    const float* W_dKV     = (const float*)d_in[5];
    const float* kv_norm_w = (const float*)d_in[6];
    const float* W_ukv     = (const float*)d_in[7];
    const float* W_o       = (const float*)d_in[8];
    float* out = (float*)d_out;

    float *qlat, *q, *ckv, *kv, *attn;
    cudaGetSymbolAddress((void**)&qlat, g_qlat);
    cudaGetSymbolAddress((void**)&q,    g_q);
    cudaGetSymbolAddress((void**)&ckv,  g_ckv);
    cudaGetSymbolAddress((void**)&kv,   g_kv);
    cudaGetSymbolAddress((void**)&attn, g_attn);

    dim3 blk(256);

    // 1. q_lat = x_q @ W_dQ                [2048,512] K=2048
    sgemm_kernel<<<dim3(QLR / 64, BQL / 64, 1), blk>>>(
        x_q, W_dQ, qlat, HID, HID, QLR, QLR, 0, 0, 0);

    // 2. rmsnorm(q_lat, q_norm_w)
    rmsnorm_kernel<<<dim3(BQL, 1), 256>>>(qlat, q_norm_w, QLR, QLR, QLR);

    // 3. q_full = q_lat @ W_uQ             [2048,3072] K=512
    sgemm_kernel<<<dim3(3072 / 64, BQL / 64, 1), blk>>>(
        qlat, W_uQ, q, QLR, QLR, 3072, 3072, 0, 0, 0);

    // 4. ckv = (x_kv @ W_dKV)[:, :1024]    [8192,1024] K=2048, ldb=1088
    sgemm_kernel<<<dim3(1024 / 64, BKL / 64, 1), blk>>>(
        x_kv, W_dKV, ckv, HID, HID, 1088, 1024, 0, 0, 0);

    // 5. rmsnorm per group (8192 rows x 4 segs of 256)
    rmsnorm_kernel<<<dim3(BKL, GG), 256>>>(ckv, kv_norm_w, LAT, GG * LAT, LAT);

    // 6. kv[g] = ckv[:, g*256:+256] @ W_ukv[g]   z-batched over 4 groups
    sgemm_kernel<<<dim3(1024 / 64, BKL / 64, GG), blk>>>(
        ckv, W_ukv, kv, LAT, GG * LAT, 1024, HH * 2 * HD,
        (long long)LAT, (long long)LAT * 1024, (long long)1024);

    // 7. flash attention
    cudaFuncSetAttribute(flash_kernel, cudaFuncAttributeMaxDynamicSharedMemorySize, FA_SMEM);
    flash_kernel<<<dim3(QL / 64, HH, BB), blk, FA_SMEM>>>(q, kv, attn);

    // 8. out = attn @ W_o                  [2048,2048] K=2048
    sgemm_kernel<<<dim3(HID / 64, BQL / 64, 1), blk>>>(
        attn, W_o, out, HH * HD, HH * HD, HID, HID, 0, 0, 0);
}

// round 5
// speedup vs baseline: 2.5496x; 2.5496x over previous
#include <cuda_runtime.h>
#include <cuda_bf16.h>
#include <stdint.h>

typedef __nv_bfloat16 bf16;

#define BB 2
#define QL 1024
#define KL 4096
#define HID 2048
#define HH 16
#define HD 128
#define GG 4
#define QLR 512
#define LAT 256
#define BQL (BB*QL)
#define BKL (BB*KL)

__device__ float g_qlat[BQL * QLR];
__device__ float g_ckv [BKL * (GG*LAT)];

__device__ bf16 s_xq_hi [BQL*HID],    s_xq_lo [BQL*HID];
__device__ bf16 s_xkv_hi[BKL*HID],    s_xkv_lo[BKL*HID];
__device__ bf16 s_qlat_hi[BQL*QLR],   s_qlat_lo[BQL*QLR];
__device__ bf16 s_ckv_hi[BKL*GG*LAT], s_ckv_lo[BKL*GG*LAT];
__device__ bf16 s_q_hi  [BQL*3072],   s_q_lo  [BQL*3072];
__device__ bf16 s_kv_hi [(long long)BKL*4096], s_kv_lo [(long long)BKL*4096];
__device__ bf16 s_attn_hi[BQL*2048],  s_attn_lo[BQL*2048];
__device__ bf16 w_dq_hi [QLR*HID],     w_dq_lo [QLR*HID];
__device__ bf16 w_uq_hi [3072*QLR],    w_uq_lo [3072*QLR];
__device__ bf16 w_dkv_hi[1024*HID],    w_dkv_lo[1024*HID];
__device__ bf16 w_ukv_hi[GG*1024*LAT], w_ukv_lo[GG*1024*LAT];
__device__ bf16 w_o_hi  [HID*2048],    w_o_lo  [HID*2048];

__device__ __forceinline__ uint32_t smem_u32(const void* p) {
    uint32_t a;
    asm("{ .reg .u64 t; cvta.to.shared.u64 t, %1; cvt.u32.u64 %0, t; }" : "=r"(a) : "l"(p));
    return a;
}
__device__ __forceinline__ void cpa16(uint32_t dst, const void* src) {
    asm volatile("cp.async.cg.shared.global [%0], [%1], 16;" :: "r"(dst), "l"(src));
}
#define CP_COMMIT() asm volatile("cp.async.commit_group;")
#define CP_WAIT0()  asm volatile("cp.async.wait_group 0;")
#define CP_WAIT1()  asm volatile("cp.async.wait_group 1;")

__device__ __forceinline__ void ldsm4(uint32_t* r, uint32_t a) {
    asm volatile("ldmatrix.sync.aligned.m8n8.x4.shared.b16 {%0,%1,%2,%3}, [%4];"
        : "=r"(r[0]), "=r"(r[1]), "=r"(r[2]), "=r"(r[3]) : "r"(a));
}
__device__ __forceinline__ void ldsm4t(uint32_t* r, uint32_t a) {
    asm volatile("ldmatrix.sync.aligned.m8n8.x4.trans.shared.b16 {%0,%1,%2,%3}, [%4];"
        : "=r"(r[0]), "=r"(r[1]), "=r"(r[2]), "=r"(r[3]) : "r"(a));
}
__device__ __forceinline__ void mmabf(float* c, const uint32_t* a, uint32_t b0, uint32_t b1) {
    asm volatile(
        "mma.sync.aligned.m16n8k16.row.col.f32.bf16.bf16.f32 "
        "{%0,%1,%2,%3}, {%4,%5,%6,%7}, {%8,%9}, {%0,%1,%2,%3};"
        : "+f"(c[0]), "+f"(c[1]), "+f"(c[2]), "+f"(c[3])
        : "r"(a[0]), "r"(a[1]), "r"(a[2]), "r"(a[3]), "r"(b0), "r"(b1));
}
__device__ __forceinline__ void split1(float x, bf16& h, bf16& l) {
    h = __float2bfloat16(x);
    l = __float2bfloat16(x - __bfloat162float(h));
}
__device__ __forceinline__ void split2(float a, float b, uint32_t& hi, uint32_t& lo) {
    bf16 ha, la, hb, lb;
    split1(a, ha, la); split1(b, hb, lb);
    __nv_bfloat162 H = __halves2bfloat162(ha, hb), L = __halves2bfloat162(la, lb);
    hi = *reinterpret_cast<uint32_t*>(&H);
    lo = *reinterpret_cast<uint32_t*>(&L);
}

// ---------------- split kernels ----------------
__global__ void split_kernel(const float* __restrict__ A, bf16* __restrict__ hi,
                             bf16* __restrict__ lo, long long n4)
{
    long long i = blockIdx.x * (long long)blockDim.x + threadIdx.x;
    long long st = (long long)gridDim.x * blockDim.x;
    for (; i < n4; i += st) {
        float4 v = ((const float4*)A)[i];
        uint32_t h0, l0, h1, l1;
        split2(v.x, v.y, h0, l0); split2(v.z, v.w, h1, l1);
        ((uint32_t*)hi)[2*i] = h0; ((uint32_t*)hi)[2*i+1] = h1;
        ((uint32_t*)lo)[2*i] = l0; ((uint32_t*)lo)[2*i+1] = l1;
    }
}

__global__ void splitT_kernel(const float* __restrict__ B, bf16* __restrict__ hiT,
                              bf16* __restrict__ loT, int ldb, int ldt,
                              long long sB, long long sO)
{
    B += blockIdx.z * sB; hiT += blockIdx.z * sO; loT += blockIdx.z * sO;
    __shared__ float t[32][33];
    int tx = threadIdx.x, ty = threadIdx.y;
    int n0 = blockIdx.x * 32, k0 = blockIdx.y * 32;
#pragma unroll
    for (int j = ty; j < 32; j += 8)
        t[j][tx] = B[(long long)(k0 + j) * ldb + n0 + tx];
    __syncthreads();
#pragma unroll
    for (int j = ty; j < 32; j += 8) {
        bf16 h, l;
        split1(t[tx][j], h, l);
        hiT[(long long)(n0 + j) * ldt + k0 + tx] = h;
        loT[(long long)(n0 + j) * ldt + k0 + tx] = l;
    }
}

// ---------------- rmsnorm + split ----------------
__global__ void rmsnorm_split(const float* __restrict__ x, const float* __restrict__ w,
                              bf16* __restrict__ hi, bf16* __restrict__ lo,
                              int n, int rowStride, int segStride)
{
    long long off = (long long)blockIdx.x * rowStride + (long long)blockIdx.y * segStride;
    const float* p = x + off;
    const float* wp = w + (long long)blockIdx.y * n;
    __shared__ float red[8]; __shared__ float rs;
    float s = 0.f;
    for (int i = threadIdx.x; i < n; i += 256) { float v = p[i]; s += v * v; }
#pragma unroll
    for (int o = 16; o; o >>= 1) s += __shfl_xor_sync(~0u, s, o);
    if ((threadIdx.x & 31) == 0) red[threadIdx.x >> 5] = s;
    __syncthreads();
    if (threadIdx.x == 0) {
        float t = 0.f;
#pragma unroll
        for (int i = 0; i < 8; i++) t += red[i];
        rs = rsqrtf(t / (float)n + 1e-6f);
    }
    __syncthreads();
    float r = rs;
    for (int i = threadIdx.x; i < n; i += 256) {
        bf16 h, l;
        split1(p[i] * r * wp[i], h, l);
        hi[off + i] = h; lo[off + i] = l;
    }
}

// =================================================================
// split-bf16 HMMA GEMM: C[M,N] = A[M,K] * B[N,K]^T
// 128x128 tile, BK=32, 256 thr (8 warps 2x4, warp tile 64x32)
// =================================================================
#define GR 80
#define GT (128*GR)
#define GSTG (4*GT)
#define GEMM_SMEM (2*GSTG)

#define GLOAD(stg, k0) do {                                   \
    uint32_t _d = (stg) + sro;                                \
    _Pragma("unroll")                                         \
    for (int _j = 0; _j < 2; _j++) {                          \
        int _e = lc * 16 + _j * 8;                            \
        cpa16(_d + _j*16,        gAh + (k0) + _e);            \
        cpa16(_d + GT + _j*16,   gAl + (k0) + _e);            \
        cpa16(_d + 2*GT + _j*16, gBh + (k0) + _e);            \
        cpa16(_d + 3*GT + _j*16, gBl + (k0) + _e);            \
    }                                                         \
} while (0)

__global__ __launch_bounds__(256, 1) void hgemm(
    const bf16* __restrict__ Ah, const bf16* __restrict__ Al, int lda,
    const bf16* __restrict__ Bh, const bf16* __restrict__ Bl, int ldb,
    float* Cf, bf16* Chi, bf16* Clo, int ldc, int K,
    long long sAz, long long sBz, long long sCz)
{
    extern __shared__ char smc[];
    const uint32_t sb = smem_u32(smc);
    const int tid = threadIdx.x, lane = tid & 31, wid = tid >> 5;
    const int m0 = blockIdx.y * 128, n0 = blockIdx.x * 128;
    const int wm = wid >> 2, wn = wid & 3;

    Ah += blockIdx.z * sAz;  Al += blockIdx.z * sAz;
    Bh += blockIdx.z * sBz;  Bl += blockIdx.z * sBz;
    long long coff = blockIdx.z * sCz;

    const int lrow = tid >> 1, lc = tid & 1;
    const bf16* gAh = Ah + (long long)(m0 + lrow) * lda;
    const bf16* gAl = Al + (long long)(m0 + lrow) * lda;
    const bf16* gBh = Bh + (long long)(n0 + lrow) * ldb;
    const bf16* gBl = Bl + (long long)(n0 + lrow) * ldb;
    const uint32_t sro = sb + lrow * GR + lc * 32;

    float acc[4][4][4];
#pragma unroll
    for (int i = 0; i < 4; i++)
#pragma unroll
        for (int j = 0; j < 4; j++)
#pragma unroll
            for (int k = 0; k < 4; k++) acc[i][j][k] = 0.f;

    const uint32_t a_base = sb + (wm * 64 + (lane & 15)) * GR + (lane >> 4) * 16;
    const uint32_t b_base = sb + 2 * GT +
        (wn * 32 + (lane & 7) + ((lane >> 4) << 3)) * GR + ((lane >> 3) & 1) * 16;

    const int nIter = K >> 5;
    GLOAD(0, 0);
    CP_COMMIT();

#pragma unroll 1
    for (int it = 0; it < nIter; it++) {
        const int s = it & 1;
        if (it + 1 < nIter) { GLOAD(((it + 1) & 1) * GSTG, (it + 1) << 5); CP_COMMIT(); CP_WAIT1(); }
        else CP_WAIT0();
        __syncthreads();

        const uint32_t ab = a_base + s * GSTG;
        const uint32_t bb = b_base + s * GSTG;
#pragma unroll
        for (int s2 = 0; s2 < 2; s2++) {
            uint32_t ah[4][4], al[4][4], bh[4][2], bl[4][2];
#pragma unroll
            for (int mt = 0; mt < 4; mt++) {
                ldsm4(ah[mt], ab + s2 * 32 + mt * (16 * GR));
                ldsm4(al[mt], ab + GT + s2 * 32 + mt * (16 * GR));
            }
#pragma unroll
            for (int np = 0; np < 2; np++) {
                uint32_t t[4];
                ldsm4(t, bb + s2 * 32 + np * (16 * GR));
                bh[np*2][0] = t[0]; bh[np*2][1] = t[1];
                bh[np*2+1][0] = t[2]; bh[np*2+1][1] = t[3];
                ldsm4(t, bb + GT + s2 * 32 + np * (16 * GR));
                bl[np*2][0] = t[0]; bl[np*2][1] = t[1];
                bl[np*2+1][0] = t[2]; bl[np*2+1][1] = t[3];
            }
#pragma unroll
            for (int mt = 0; mt < 4; mt++)
#pragma unroll
                for (int nf = 0; nf < 4; nf++) {
                    mmabf(acc[mt][nf], ah[mt], bh[nf][0], bh[nf][1]);
                    mmabf(acc[mt][nf], ah[mt], bl[nf][0], bl[nf][1]);
                    mmabf(acc[mt][nf], al[mt], bh[nf][0], bh[nf][1]);
                }
        }
        __syncthreads();
    }

#pragma unroll
    for (int mt = 0; mt < 4; mt++)
#pragma unroll
        for (int nf = 0; nf < 4; nf++) {
            long long row = m0 + wm * 64 + mt * 16 + (lane >> 2);
            int col = n0 + wn * 32 + nf * 8 + (lane & 3) * 2;
            const float* c = acc[mt][nf];
            if (Cf) {
                float* p = Cf + coff;
                *(float2*)(p + row * ldc + col) = make_float2(c[0], c[1]);
                *(float2*)(p + (row + 8) * ldc + col) = make_float2(c[2], c[3]);
            }
            if (Chi) {
                uint32_t h0, l0, h1, l1;
                split2(c[0], c[1], h0, l0);
                split2(c[2], c[3], h1, l1);
                *(uint32_t*)(Chi + coff + row * ldc + col) = h0;
                *(uint32_t*)(Clo + coff + row * ldc + col) = l0;
                *(uint32_t*)(Chi + coff + (row + 8) * ldc + col) = h1;
                *(uint32_t*)(Clo + coff + (row + 8) * ldc + col) = l1;
            }
        }
}

// =================================================================
// split-bf16 HMMA flash attention: BM=128, BN=64, 8 warps
// =================================================================
#define ROWB 272
#define QT   (128*ROWB)
#define KVT  (64*ROWB)
#define KVSTG (4*KVT)
#define FA_SMEM (2*QT + 2*KVSTG)   // 208896
#define SCL 0.1275174313213403f    // 1/sqrt(128) * log2(e)

#define KVLOAD(stgoff, jb) do {                                              \
    long long rg = ((long long)(bb*KL + (jb)*64 + kr)) * 4096 + hh*256 + kq*32; \
    uint32_t d = kvb + (stgoff) + kr * ROWB + kq * 64;                       \
    const bf16* s1 = KVh + rg; const bf16* s2 = KVl + rg;                    \
    _Pragma("unroll")                                                        \
    for (int _j = 0; _j < 4; _j++) {                                         \
        cpa16(d + _j*16,          s1 + _j*8);                                \
        cpa16(d + KVT + _j*16,    s2 + _j*8);                                \
        cpa16(d + 2*KVT + _j*16,  s1 + 128 + _j*8);                          \
        cpa16(d + 3*KVT + _j*16,  s2 + 128 + _j*8);                          \
    }                                                                        \
} while (0)

__global__ __launch_bounds__(256, 1) void flash(
    const bf16* __restrict__ Qh, const bf16* __restrict__ Ql,
    const bf16* __restrict__ KVh, const bf16* __restrict__ KVl,
    bf16* __restrict__ Ohi, bf16* __restrict__ Olo)
{
    extern __shared__ char smc[];
    const uint32_t sb = smem_u32(smc);
    const uint32_t kvb = sb + 2 * QT;
    const int tid = threadIdx.x, lane = tid & 31, wid = tid >> 5;
    const int qt = blockIdx.x, hh = blockIdx.y, bb = blockIdx.z;
    const int kr = tid >> 2, kq = tid & 3;

    // Q load: thread -> row tid>>1, 128B half tid&1, both hi/lo
    {
        int r = tid >> 1, hc = tid & 1;
        long long rg = ((long long)(bb*QL + qt*128 + r)) * 3072 + hh*192 + hc*64;
        uint32_t d = sb + r * ROWB + hc * 128;
#pragma unroll
        for (int j = 0; j < 8; j++) {
            cpa16(d + j*16,      Qh + rg + j*8);
            cpa16(d + QT + j*16, Ql + rg + j*8);
        }
    }
    KVLOAD(0, 0);
    CP_COMMIT();

    float O[16][4];
#pragma unroll
    for (int i = 0; i < 16; i++)
#pragma unroll
        for (int j = 0; j < 4; j++) O[i][j] = 0.f;
    float m0v = -1e30f, m1v = -1e30f, l0v = 0.f, l1v = 0.f;

    const uint32_t a_q = sb + (wid * 16 + (lane & 15)) * ROWB + (lane >> 4) * 16;
    const uint32_t b_k = kvb + ((lane & 7) + ((lane >> 4) << 3)) * ROWB + ((lane >> 3) & 1) * 16;
    const uint32_t v_t = kvb + 2 * KVT + (lane & 15) * ROWB + ((lane >> 4) << 4);

#pragma unroll 1
    for (int jb = 0; jb < KL / 64; jb++) {
        const int s = jb & 1;
        if (jb + 1 < KL / 64) { KVLOAD(((jb + 1) & 1) * KVSTG, jb + 1); CP_COMMIT(); CP_WAIT1(); }
        else CP_WAIT0();
        __syncthreads();

        // ---- S = Q K^T (split 3-pass) ----
        float S[8][4];
#pragma unroll
        for (int f = 0; f < 8; f++)
#pragma unroll
            for (int e = 0; e < 4; e++) S[f][e] = 0.f;

        const uint32_t bk = b_k + s * KVSTG;
#pragma unroll
        for (int d16 = 0; d16 < 8; d16++) {
            uint32_t qh[4], ql[4];
            ldsm4(qh, a_q + d16 * 32);
            ldsm4(ql, a_q + QT + d16 * 32);
#pragma unroll
            for (int np = 0; np < 4; np++) {
                uint32_t kh[4], kl[4];
                ldsm4(kh, bk + np * (16 * ROWB) + d16 * 32);
                ldsm4(kl, bk + KVT + np * (16 * ROWB) + d16 * 32);
                mmabf(S[np*2],   qh, kh[0], kh[1]);
                mmabf(S[np*2],   qh, kl[0], kl[1]);
                mmabf(S[np*2],   ql, kh[0], kh[1]);
                mmabf(S[np*2+1], qh, kh[2], kh[3]);
                mmabf(S[np*2+1], qh, kl[2], kl[3]);
                mmabf(S[np*2+1], ql, kh[2], kh[3]);
            }
        }

        // ---- online softmax ----
        float mloc0 = -1e30f, mloc1 = -1e30f;
#pragma unroll
        for (int f = 0; f < 8; f++) {
            S[f][0] *= SCL; S[f][1] *= SCL; S[f][2] *= SCL; S[f][3] *= SCL;
            mloc0 = fmaxf(mloc0, fmaxf(S[f][0], S[f][1]));
            mloc1 = fmaxf(mloc1, fmaxf(S[f][2], S[f][3]));
        }
        mloc0 = fmaxf(mloc0, __shfl_xor_sync(~0u, mloc0, 1));
        mloc0 = fmaxf(mloc0, __shfl_xor_sync(~0u, mloc0, 2));
        mloc1 = fmaxf(mloc1, __shfl_xor_sync(~0u, mloc1, 1));
        mloc1 = fmaxf(mloc1, __shfl_xor_sync(~0u, mloc1, 2));
        float mn0 = fmaxf(m0v, mloc0), mn1 = fmaxf(m1v, mloc1);
        float a0 = exp2f(m0v - mn0), a1 = exp2f(m1v - mn1);
        m0v = mn0; m1v = mn1;
        float sum0 = 0.f, sum1 = 0.f;
#pragma unroll
        for (int f = 0; f < 8; f++) {
            S[f][0] = exp2f(S[f][0] - mn0); S[f][1] = exp2f(S[f][1] - mn0);
            S[f][2] = exp2f(S[f][2] - mn1); S[f][3] = exp2f(S[f][3] - mn1);
            sum0 += S[f][0] + S[f][1];
            sum1 += S[f][2] + S[f][3];
        }
        sum0 += __shfl_xor_sync(~0u, sum0, 1); sum0 += __shfl_xor_sync(~0u, sum0, 2);
        sum1 += __shfl_xor_sync(~0u, sum1, 1); sum1 += __shfl_xor_sync(~0u, sum1, 2);
        l0v = l0v * a0 + sum0; l1v = l1v * a1 + sum1;
#pragma unroll
        for (int i = 0; i < 16; i++) {
            O[i][0] *= a0; O[i][1] *= a0; O[i][2] *= a1; O[i][3] *= a1;
        }

        // ---- O += P V (split 3-pass) ----
        const uint32_t vt = v_t + s * KVSTG;
#pragma unroll
        for (int ks = 0; ks < 4; ks++) {
            uint32_t ph[4], pl[4];
            split2(S[2*ks][0],   S[2*ks][1],   ph[0], pl[0]);
            split2(S[2*ks][2],   S[2*ks][3],   ph[1], pl[1]);
            split2(S[2*ks+1][0], S[2*ks+1][1], ph[2], pl[2]);
            split2(S[2*ks+1][2], S[2*ks+1][3], ph[3], pl[3]);
#pragma unroll
            for (int dn = 0; dn < 8; dn++) {
                uint32_t vh[4], vl[4];
                ldsm4t(vh, vt + ks * (16 * ROWB) + dn * 32);
                ldsm4t(vl, vt + KVT + ks * (16 * ROWB) + dn * 32);
                mmabf(O[dn*2],   ph, vh[0], vh[1]);
                mmabf(O[dn*2],   ph, vl[0], vl[1]);
                mmabf(O[dn*2],   pl, vh[0], vh[1]);
                mmabf(O[dn*2+1], ph, vh[2], vh[3]);
                mmabf(O[dn*2+1], ph, vl[2], vl[3]);
                mmabf(O[dn*2+1], pl, vh[2], vh[3]);
            }
        }
        __syncthreads();
    }

    // ---- epilogue ----
    float i0 = 1.f / l0v, i1 = 1.f / l1v;
    long long row0 = (long long)(bb*QL + qt*128 + wid*16 + (lane >> 2)) * 2048 + hh*128;
    int cc = (lane & 3) * 2;
#pragma unroll
    for (int nf = 0; nf < 16; nf++) {
        uint32_t h0, l0, h1, l1;
        split2(O[nf][0] * i0, O[nf][1] * i0, h0, l0);
        split2(O[nf][2] * i1, O[nf][3] * i1, h1, l1);
        long long c0 = row0 + nf*8 + cc;
        *(uint32_t*)(Ohi + c0) = h0;         *(uint32_t*)(Olo + c0) = l0;
        *(uint32_t*)(Ohi + c0 + 8*2048) = h1; *(uint32_t*)(Olo + c0 + 8*2048) = l1;
    }
}

// =================================================================
// launch
// =================================================================
extern "C" void kernel_launch(void* const* d_in, const int* in_sizes, int n_in,
                              void* d_out, int out_size)
{
    const float* x_q       = (const float*)d_in[0];
    const float* x_kv      = (const float*)d_in[1];
    const float* W_dQ      = (const float*)d_in[2];
    const float* q_norm_w  = (const float*)d_in[3];
    const float* W_uQ      = (const float*)d_in[4];
    const float* W_dKV     = (const float*)d_in[5];
    const float* kv_norm_w = (const float*)d_in[6];
    const float* W_ukv     = (const float*)d_in[7];
    const float* W_o       = (const float*)d_in[8];
    float* out = (float*)d_out;

    float *qlat, *ckv;
    cudaGetSymbolAddress((void**)&qlat, g_qlat);
    cudaGetSymbolAddress((void**)&ckv,  g_ckv);
    bf16 *xqh,*xql,*xkvh,*xkvl,*qlh,*qll,*ckvh,*ckvl,*qh,*ql2,*kvh,*kvl,*ath,*atl;
    bf16 *wdqh,*wdql,*wuqh,*wuql,*wdkvh,*wdkvl,*wukvh,*wukvl,*woh,*wol;
    cudaGetSymbolAddress((void**)&xqh,  s_xq_hi);   cudaGetSymbolAddress((void**)&xql,  s_xq_lo);
    cudaGetSymbolAddress((void**)&xkvh, s_xkv_hi);  cudaGetSymbolAddress((void**)&xkvl, s_xkv_lo);
    cudaGetSymbolAddress((void**)&qlh,  s_qlat_hi); cudaGetSymbolAddress((void**)&qll,  s_qlat_lo);
    cudaGetSymbolAddress((void**)&ckvh, s_ckv_hi);  cudaGetSymbolAddress((void**)&ckvl, s_ckv_lo);
    cudaGetSymbolAddress((void**)&qh,   s_q_hi);    cudaGetSymbolAddress((void**)&ql2,  s_q_lo);
    cudaGetSymbolAddress((void**)&kvh,  s_kv_hi);   cudaGetSymbolAddress((void**)&kvl,  s_kv_lo);
    cudaGetSymbolAddress((void**)&ath,  s_attn_hi); cudaGetSymbolAddress((void**)&atl,  s_attn_lo);
    cudaGetSymbolAddress((void**)&wdqh, w_dq_hi);   cudaGetSymbolAddress((void**)&wdql, w_dq_lo);
    cudaGetSymbolAddress((void**)&wuqh, w_uq_hi);   cudaGetSymbolAddress((void**)&wuql, w_uq_lo);
    cudaGetSymbolAddress((void**)&wdkvh, w_dkv_hi); cudaGetSymbolAddress((void**)&wdkvl, w_dkv_lo);
    cudaGetSymbolAddress((void**)&wukvh, w_ukv_hi); cudaGetSymbolAddress((void**)&wukvl, w_ukv_lo);
    cudaGetSymbolAddress((void**)&woh,  w_o_hi);    cudaGetSymbolAddress((void**)&wol,  w_o_lo);

    cudaFuncSetAttribute(hgemm, cudaFuncAttributeMaxDynamicSharedMemorySize, GEMM_SMEM);
    cudaFuncSetAttribute(flash, cudaFuncAttributeMaxDynamicSharedMemorySize, FA_SMEM);

    dim3 tb(32, 8);
    split_kernel<<<2048, 256>>>(x_q,  xqh,  xql,  (long long)BQL*HID/4);
    split_kernel<<<4096, 256>>>(x_kv, xkvh, xkvl, (long long)BKL*HID/4);
    splitT_kernel<<<dim3(QLR/32, HID/32), tb>>>(W_dQ,  wdqh,  wdql,  QLR,  HID, 0, 0);
    splitT_kernel<<<dim3(3072/32, QLR/32), tb>>>(W_uQ,  wuqh,  wuql,  3072, QLR, 0, 0);
    splitT_kernel<<<dim3(1024/32, HID/32), tb>>>(W_dKV, wdkvh, wdkvl, 1088, HID, 0, 0);
    splitT_kernel<<<dim3(1024/32, LAT/32, GG), tb>>>(W_ukv, wukvh, wukvl, 1024, LAT,
                                                     (long long)LAT*1024, (long long)1024*LAT);
    splitT_kernel<<<dim3(HID/32, 2048/32), tb>>>(W_o, woh, wol, HID, 2048, 0, 0);

    // 1. q_lat = x_q @ W_dQ      [2048 x 512] K=2048 -> fp32
    hgemm<<<dim3(4, 16), 256, GEMM_SMEM>>>(xqh, xql, HID, wdqh, wdql, HID,
                                           qlat, nullptr, nullptr, QLR, HID, 0, 0, 0);
    // 2. rmsnorm + split
    rmsnorm_split<<<dim3(BQL, 1), 256>>>(qlat, q_norm_w, qlh, qll, QLR, QLR, QLR);
    // 3. q = q_lat @ W_uQ        [2048 x 3072] K=512 -> bf16 hi/lo
    hgemm<<<dim3(24, 16), 256, GEMM_SMEM>>>(qlh, qll, QLR, wuqh, wuql, QLR,
                                            nullptr, qh, ql2, 3072, QLR, 0, 0, 0);
    // 4. ckv = (x_kv @ W_dKV)[:, :1024]  [8192 x 1024] K=2048 -> fp32
    hgemm<<<dim3(8, 64), 256, GEMM_SMEM>>>(xkvh, xkvl, HID, wdkvh, wdkvl, HID,
                                           ckv, nullptr, nullptr, GG*LAT, HID, 0, 0, 0);
    // 5. rmsnorm per group + split
    rmsnorm_split<<<dim3(BKL, GG), 256>>>(ckv, kv_norm_w, ckvh, ckvl, LAT, GG*LAT, LAT);
    // 6. kv[g] = ckv_g @ W_ukv[g]^T   [8192 x 1024] K=256, z=4 -> bf16 hi/lo
    hgemm<<<dim3(8, 64, GG), 256, GEMM_SMEM>>>(ckvh, ckvl, GG*LAT, wukvh, wukvl, LAT,
                                               nullptr, kvh, kvl, 4096, LAT,
                                               (long long)LAT, (long long)1024*LAT, (long long)1024);
    // 7. flash attention -> attn hi/lo
    flash<<<dim3(QL/128, HH, BB), 256, FA_SMEM>>>(qh, ql2, kvh, kvl, ath, atl);
    // 8. out = attn @ W_o        [2048 x 2048] K=2048 -> fp32
    hgemm<<<dim3(16, 16), 256, GEMM_SMEM>>>(ath, atl, 2048, woh, wol, HID,
                                            out, nullptr, nullptr, HID, 2048, 0, 0, 0);
}

// round 6
// speedup vs baseline: 2.7532x; 1.0799x over previous
#include <cuda_runtime.h>
#include <cuda_bf16.h>
#include <stdint.h>

typedef __nv_bfloat16 bf16;

#define BB 2
#define QL 1024
#define KL 4096
#define HID 2048
#define HH 16
#define HD 128
#define GG 4
#define QLR 512
#define LAT 256
#define BQL (BB*QL)
#define BKL (BB*KL)

__device__ float g_qlat[BQL * QLR];
__device__ float g_ckv [BKL * (GG*LAT)];

__device__ bf16 s_xq_hi [BQL*HID],    s_xq_lo [BQL*HID];
__device__ bf16 s_xkv_hi[BKL*HID],    s_xkv_lo[BKL*HID];
__device__ bf16 s_qlat_hi[BQL*QLR],   s_qlat_lo[BQL*QLR];
__device__ bf16 s_ckv_hi[BKL*GG*LAT], s_ckv_lo[BKL*GG*LAT];
__device__ bf16 s_q_hi  [BQL*3072],   s_q_lo  [BQL*3072];
__device__ bf16 s_kv_hi [(long long)BKL*4096], s_kv_lo [(long long)BKL*4096];
__device__ bf16 s_attn_hi[BQL*2048],  s_attn_lo[BQL*2048];
__device__ bf16 w_dq_hi [QLR*HID],     w_dq_lo [QLR*HID];
__device__ bf16 w_uq_hi [3072*QLR],    w_uq_lo [3072*QLR];
__device__ bf16 w_dkv_hi[1024*HID],    w_dkv_lo[1024*HID];
__device__ bf16 w_ukv_hi[GG*1024*LAT], w_ukv_lo[GG*1024*LAT];
__device__ bf16 w_o_hi  [HID*2048],    w_o_lo  [HID*2048];

__device__ __forceinline__ uint32_t smem_u32(const void* p) {
    uint32_t a;
    asm("{ .reg .u64 t; cvta.to.shared.u64 t, %1; cvt.u32.u64 %0, t; }" : "=r"(a) : "l"(p));
    return a;
}
__device__ __forceinline__ void cpa16(uint32_t dst, const void* src) {
    asm volatile("cp.async.cg.shared.global [%0], [%1], 16;" :: "r"(dst), "l"(src));
}
#define CP_COMMIT() asm volatile("cp.async.commit_group;")
#define CP_WAIT0()  asm volatile("cp.async.wait_group 0;")
#define CP_WAIT1()  asm volatile("cp.async.wait_group 1;")
#define CP_WAIT2()  asm volatile("cp.async.wait_group 2;")

__device__ __forceinline__ void ldsm4(uint32_t* r, uint32_t a) {
    asm volatile("ldmatrix.sync.aligned.m8n8.x4.shared.b16 {%0,%1,%2,%3}, [%4];"
        : "=r"(r[0]), "=r"(r[1]), "=r"(r[2]), "=r"(r[3]) : "r"(a));
}
__device__ __forceinline__ void ldsm4t(uint32_t* r, uint32_t a) {
    asm volatile("ldmatrix.sync.aligned.m8n8.x4.trans.shared.b16 {%0,%1,%2,%3}, [%4];"
        : "=r"(r[0]), "=r"(r[1]), "=r"(r[2]), "=r"(r[3]) : "r"(a));
}
__device__ __forceinline__ void mmabf(float* c, const uint32_t* a, uint32_t b0, uint32_t b1) {
    asm volatile(
        "mma.sync.aligned.m16n8k16.row.col.f32.bf16.bf16.f32 "
        "{%0,%1,%2,%3}, {%4,%5,%6,%7}, {%8,%9}, {%0,%1,%2,%3};"
        : "+f"(c[0]), "+f"(c[1]), "+f"(c[2]), "+f"(c[3])
        : "r"(a[0]), "r"(a[1]), "r"(a[2]), "r"(a[3]), "r"(b0), "r"(b1));
}
__device__ __forceinline__ void split1(float x, bf16& h, bf16& l) {
    h = __float2bfloat16(x);
    l = __float2bfloat16(x - __bfloat162float(h));
}
__device__ __forceinline__ void split2(float a, float b, uint32_t& hi, uint32_t& lo) {
    bf16 ha, la, hb, lb;
    split1(a, ha, la); split1(b, hb, lb);
    __nv_bfloat162 H = __halves2bfloat162(ha, hb), L = __halves2bfloat162(la, lb);
    hi = *reinterpret_cast<uint32_t*>(&H);
    lo = *reinterpret_cast<uint32_t*>(&L);
}

// ---------------- split kernels ----------------
__global__ void split_kernel(const float* __restrict__ A, bf16* __restrict__ hi,
                             bf16* __restrict__ lo, long long n4)
{
    long long i = blockIdx.x * (long long)blockDim.x + threadIdx.x;
    long long st = (long long)gridDim.x * blockDim.x;
    for (; i < n4; i += st) {
        float4 v = ((const float4*)A)[i];
        uint32_t h0, l0, h1, l1;
        split2(v.x, v.y, h0, l0); split2(v.z, v.w, h1, l1);
        ((uint32_t*)hi)[2*i] = h0; ((uint32_t*)hi)[2*i+1] = h1;
        ((uint32_t*)lo)[2*i] = l0; ((uint32_t*)lo)[2*i+1] = l1;
    }
}

__global__ void splitT_kernel(const float* __restrict__ B, bf16* __restrict__ hiT,
                              bf16* __restrict__ loT, int ldb, int ldt,
                              long long sB, long long sO)
{
    B += blockIdx.z * sB; hiT += blockIdx.z * sO; loT += blockIdx.z * sO;
    __shared__ float t[32][33];
    int tx = threadIdx.x, ty = threadIdx.y;
    int n0 = blockIdx.x * 32, k0 = blockIdx.y * 32;
#pragma unroll
    for (int j = ty; j < 32; j += 8)
        t[j][tx] = B[(long long)(k0 + j) * ldb + n0 + tx];
    __syncthreads();
#pragma unroll
    for (int j = ty; j < 32; j += 8) {
        bf16 h, l;
        split1(t[tx][j], h, l);
        hiT[(long long)(n0 + j) * ldt + k0 + tx] = h;
        loT[(long long)(n0 + j) * ldt + k0 + tx] = l;
    }
}

// ---------------- rmsnorm + split ----------------
__global__ void rmsnorm_split(const float* __restrict__ x, const float* __restrict__ w,
                              bf16* __restrict__ hi, bf16* __restrict__ lo,
                              int n, int rowStride, int segStride)
{
    long long off = (long long)blockIdx.x * rowStride + (long long)blockIdx.y * segStride;
    const float* p = x + off;
    const float* wp = w + (long long)blockIdx.y * n;
    __shared__ float red[8]; __shared__ float rs;
    float s = 0.f;
    for (int i = threadIdx.x; i < n; i += 256) { float v = p[i]; s += v * v; }
#pragma unroll
    for (int o = 16; o; o >>= 1) s += __shfl_xor_sync(~0u, s, o);
    if ((threadIdx.x & 31) == 0) red[threadIdx.x >> 5] = s;
    __syncthreads();
    if (threadIdx.x == 0) {
        float t = 0.f;
#pragma unroll
        for (int i = 0; i < 8; i++) t += red[i];
        rs = rsqrtf(t / (float)n + 1e-6f);
    }
    __syncthreads();
    float r = rs;
    for (int i = threadIdx.x; i < n; i += 256) {
        bf16 h, l;
        split1(p[i] * r * wp[i], h, l);
        hi[off + i] = h; lo[off + i] = l;
    }
}

// =================================================================
// split-bf16 HMMA GEMM: C[M,N] = A[M,K] * B[N,K]^T
// 128x128 tile, BK=32, 256 thr (8 warps 2x4), 2 CTAs/SM
// =================================================================
#define GR 80
#define GT (128*GR)
#define GSTG (4*GT)
#define GEMM_SMEM (2*GSTG)

#define GLOAD(stg, k0) do {                                   \
    uint32_t _d = (stg) + sro;                                \
    _Pragma("unroll")                                         \
    for (int _j = 0; _j < 2; _j++) {                          \
        int _e = lc * 16 + _j * 8;                            \
        cpa16(_d + _j*16,        gAh + (k0) + _e);            \
        cpa16(_d + GT + _j*16,   gAl + (k0) + _e);            \
        cpa16(_d + 2*GT + _j*16, gBh + (k0) + _e);            \
        cpa16(_d + 3*GT + _j*16, gBl + (k0) + _e);            \
    }                                                         \
} while (0)

__global__ __launch_bounds__(256, 2) void hgemm(
    const bf16* __restrict__ Ah, const bf16* __restrict__ Al, int lda,
    const bf16* __restrict__ Bh, const bf16* __restrict__ Bl, int ldb,
    float* Cf, bf16* Chi, bf16* Clo, int ldc, int K,
    long long sAz, long long sBz, long long sCz)
{
    extern __shared__ char smc[];
    const uint32_t sb = smem_u32(smc);
    const int tid = threadIdx.x, lane = tid & 31, wid = tid >> 5;
    const int m0 = blockIdx.y * 128, n0 = blockIdx.x * 128;
    const int wm = wid >> 2, wn = wid & 3;

    Ah += blockIdx.z * sAz;  Al += blockIdx.z * sAz;
    Bh += blockIdx.z * sBz;  Bl += blockIdx.z * sBz;
    long long coff = blockIdx.z * sCz;

    const int lrow = tid >> 1, lc = tid & 1;
    const bf16* gAh = Ah + (long long)(m0 + lrow) * lda;
    const bf16* gAl = Al + (long long)(m0 + lrow) * lda;
    const bf16* gBh = Bh + (long long)(n0 + lrow) * ldb;
    const bf16* gBl = Bl + (long long)(n0 + lrow) * ldb;
    const uint32_t sro = sb + lrow * GR + lc * 32;

    float acc[4][4][4];
#pragma unroll
    for (int i = 0; i < 4; i++)
#pragma unroll
        for (int j = 0; j < 4; j++)
#pragma unroll
            for (int k = 0; k < 4; k++) acc[i][j][k] = 0.f;

    const uint32_t a_base = sb + (wm * 64 + (lane & 15)) * GR + (lane >> 4) * 16;
    const uint32_t b_base = sb + 2 * GT +
        (wn * 32 + (lane & 7) + ((lane >> 4) << 3)) * GR + ((lane >> 3) & 1) * 16;

    const int nIter = K >> 5;
    GLOAD(0, 0);
    CP_COMMIT();

#pragma unroll 1
    for (int it = 0; it < nIter; it++) {
        const int s = it & 1;
        if (it + 1 < nIter) { GLOAD(((it + 1) & 1) * GSTG, (it + 1) << 5); CP_COMMIT(); CP_WAIT1(); }
        else CP_WAIT0();
        __syncthreads();

        const uint32_t ab = a_base + s * GSTG;
        const uint32_t bb = b_base + s * GSTG;
#pragma unroll
        for (int s2 = 0; s2 < 2; s2++) {
            uint32_t ah[4][4], al[4][4], bh[4][2], bl[4][2];
#pragma unroll
            for (int mt = 0; mt < 4; mt++) {
                ldsm4(ah[mt], ab + s2 * 32 + mt * (16 * GR));
                ldsm4(al[mt], ab + GT + s2 * 32 + mt * (16 * GR));
            }
#pragma unroll
            for (int np = 0; np < 2; np++) {
                uint32_t t[4];
                ldsm4(t, bb + s2 * 32 + np * (16 * GR));
                bh[np*2][0] = t[0]; bh[np*2][1] = t[1];
                bh[np*2+1][0] = t[2]; bh[np*2+1][1] = t[3];
                ldsm4(t, bb + GT + s2 * 32 + np * (16 * GR));
                bl[np*2][0] = t[0]; bl[np*2][1] = t[1];
                bl[np*2+1][0] = t[2]; bl[np*2+1][1] = t[3];
            }
#pragma unroll
            for (int mt = 0; mt < 4; mt++)
#pragma unroll
                for (int nf = 0; nf < 4; nf++) {
                    mmabf(acc[mt][nf], ah[mt], bh[nf][0], bh[nf][1]);
                    mmabf(acc[mt][nf], ah[mt], bl[nf][0], bl[nf][1]);
                    mmabf(acc[mt][nf], al[mt], bh[nf][0], bh[nf][1]);
                }
        }
        __syncthreads();
    }

#pragma unroll
    for (int mt = 0; mt < 4; mt++)
#pragma unroll
        for (int nf = 0; nf < 4; nf++) {
            long long row = m0 + wm * 64 + mt * 16 + (lane >> 2);
            int col = n0 + wn * 32 + nf * 8 + (lane & 3) * 2;
            const float* c = acc[mt][nf];
            if (Cf) {
                float* p = Cf + coff;
                *(float2*)(p + row * ldc + col) = make_float2(c[0], c[1]);
                *(float2*)(p + (row + 8) * ldc + col) = make_float2(c[2], c[3]);
            }
            if (Chi) {
                uint32_t h0, l0, h1, l1;
                split2(c[0], c[1], h0, l0);
                split2(c[2], c[3], h1, l1);
                *(uint32_t*)(Chi + coff + row * ldc + col) = h0;
                *(uint32_t*)(Clo + coff + row * ldc + col) = l0;
                *(uint32_t*)(Chi + coff + (row + 8) * ldc + col) = h1;
                *(uint32_t*)(Clo + coff + (row + 8) * ldc + col) = l1;
            }
        }
}

// =================================================================
// split-bf16 HMMA flash attention: BM=128, BN=64, 8 warps
// Q fragments hoisted to registers; 3-stage KV ring (stage2 = Q region)
// =================================================================
#define ROWB 272
#define QT   (128*ROWB)
#define KVT  (64*ROWB)
#define KVSTG (4*KVT)          // == 2*QT
#define FA_SMEM (3*KVSTG)      // 208896
#define SCL 0.1275174313213403f  // 1/sqrt(128) * log2(e)
#define NIT (KL/64)

#define KVLOAD(stb, jb) do {                                                 \
    long long rg = ((long long)(bb*KL + (jb)*64 + kr)) * 4096 + hh*256 + kq*32; \
    uint32_t d = (stb) + kr * ROWB + kq * 64;                                \
    const bf16* s1 = KVh + rg; const bf16* s2 = KVl + rg;                    \
    _Pragma("unroll")                                                        \
    for (int _j = 0; _j < 4; _j++) {                                         \
        cpa16(d + _j*16,          s1 + _j*8);                                \
        cpa16(d + KVT + _j*16,    s2 + _j*8);                                \
        cpa16(d + 2*KVT + _j*16,  s1 + 128 + _j*8);                          \
        cpa16(d + 3*KVT + _j*16,  s2 + 128 + _j*8);                          \
    }                                                                        \
} while (0)

__global__ __launch_bounds__(256, 1) void flash(
    const bf16* __restrict__ Qh, const bf16* __restrict__ Ql,
    const bf16* __restrict__ KVh, const bf16* __restrict__ KVl,
    bf16* __restrict__ Ohi, bf16* __restrict__ Olo)
{
    extern __shared__ char smc[];
    const uint32_t sb = smem_u32(smc);
    const int tid = threadIdx.x, lane = tid & 31, wid = tid >> 5;
    const int qt = blockIdx.x, hh = blockIdx.y, bb = blockIdx.z;
    const int kr = tid >> 2, kq = tid & 3;

    // stage base: s=0 -> sb+KVSTG, s=1 -> sb+2*KVSTG, s=2 -> sb (Q region reused)
    // prologue: Q into [sb, 2*QT) (group 0)
    {
        int r = tid >> 1, hc = tid & 1;
        long long rg = ((long long)(bb*QL + qt*128 + r)) * 3072 + hh*192 + hc*64;
        uint32_t d = sb + r * ROWB + hc * 128;
#pragma unroll
        for (int j = 0; j < 8; j++) {
            cpa16(d + j*16,      Qh + rg + j*8);
            cpa16(d + QT + j*16, Ql + rg + j*8);
        }
    }
    CP_COMMIT();
    KVLOAD(sb + KVSTG, 0);     CP_COMMIT();   // group 1 -> stage 0
    KVLOAD(sb + 2*KVSTG, 1);   CP_COMMIT();   // group 2 -> stage 1

    float O[16][4];
#pragma unroll
    for (int i = 0; i < 16; i++)
#pragma unroll
        for (int j = 0; j < 4; j++) O[i][j] = 0.f;
    float m0v = -1e30f, m1v = -1e30f, l0v = 0.f, l1v = 0.f;

    const uint32_t a_q = sb + (wid * 16 + (lane & 15)) * ROWB + (lane >> 4) * 16;
    const uint32_t bk_rel = ((lane & 7) + ((lane >> 4) << 3)) * ROWB + ((lane >> 3) & 1) * 16;
    const uint32_t vt_rel = 2 * KVT + (lane & 15) * ROWB + ((lane >> 4) << 4);

    // hoist Q fragments (Q group done once <=2 groups pending)
    CP_WAIT2();
    __syncthreads();
    uint32_t qfh[8][4], qfl[8][4];
#pragma unroll
    for (int d16 = 0; d16 < 8; d16++) {
        ldsm4(qfh[d16], a_q + d16 * 32);
        ldsm4(qfl[d16], a_q + QT + d16 * 32);
    }
    __syncthreads();   // everyone done reading Q before stage2 overwrites it

#pragma unroll 1
    for (int jb = 0; jb < NIT; jb++) {
        const int s = jb % 3;
        const uint32_t stb = sb + ((s + 1) % 3) * KVSTG;
        if (jb + 2 < NIT) {
            const int s2i = (jb + 2) % 3;
            KVLOAD(sb + ((s2i + 1) % 3) * KVSTG, jb + 2);
            CP_COMMIT();
        }
        if (jb < NIT - 2) CP_WAIT2();
        else if (jb == NIT - 2) CP_WAIT1();
        else CP_WAIT0();
        __syncthreads();

        // ---- S = Q K^T (split 3-pass) ----
        float S[8][4];
#pragma unroll
        for (int f = 0; f < 8; f++)
#pragma unroll
            for (int e = 0; e < 4; e++) S[f][e] = 0.f;

        const uint32_t bk = stb + bk_rel;
#pragma unroll
        for (int d16 = 0; d16 < 8; d16++) {
#pragma unroll
            for (int np = 0; np < 4; np++) {
                uint32_t kh[4], kl[4];
                ldsm4(kh, bk + np * (16 * ROWB) + d16 * 32);
                ldsm4(kl, bk + KVT + np * (16 * ROWB) + d16 * 32);
                mmabf(S[np*2],   qfh[d16], kh[0], kh[1]);
                mmabf(S[np*2],   qfh[d16], kl[0], kl[1]);
                mmabf(S[np*2],   qfl[d16], kh[0], kh[1]);
                mmabf(S[np*2+1], qfh[d16], kh[2], kh[3]);
                mmabf(S[np*2+1], qfh[d16], kl[2], kl[3]);
                mmabf(S[np*2+1], qfl[d16], kh[2], kh[3]);
            }
        }

        // ---- online softmax ----
        float mloc0 = -1e30f, mloc1 = -1e30f;
#pragma unroll
        for (int f = 0; f < 8; f++) {
            S[f][0] *= SCL; S[f][1] *= SCL; S[f][2] *= SCL; S[f][3] *= SCL;
            mloc0 = fmaxf(mloc0, fmaxf(S[f][0], S[f][1]));
            mloc1 = fmaxf(mloc1, fmaxf(S[f][2], S[f][3]));
        }
        mloc0 = fmaxf(mloc0, __shfl_xor_sync(~0u, mloc0, 1));
        mloc0 = fmaxf(mloc0, __shfl_xor_sync(~0u, mloc0, 2));
        mloc1 = fmaxf(mloc1, __shfl_xor_sync(~0u, mloc1, 1));
        mloc1 = fmaxf(mloc1, __shfl_xor_sync(~0u, mloc1, 2));
        float mn0 = fmaxf(m0v, mloc0), mn1 = fmaxf(m1v, mloc1);
        float a0 = exp2f(m0v - mn0), a1 = exp2f(m1v - mn1);
        m0v = mn0; m1v = mn1;
        float sum0 = 0.f, sum1 = 0.f;
#pragma unroll
        for (int f = 0; f < 8; f++) {
            S[f][0] = exp2f(S[f][0] - mn0); S[f][1] = exp2f(S[f][1] - mn0);
            S[f][2] = exp2f(S[f][2] - mn1); S[f][3] = exp2f(S[f][3] - mn1);
            sum0 += S[f][0] + S[f][1];
            sum1 += S[f][2] + S[f][3];
        }
        sum0 += __shfl_xor_sync(~0u, sum0, 1); sum0 += __shfl_xor_sync(~0u, sum0, 2);
        sum1 += __shfl_xor_sync(~0u, sum1, 1); sum1 += __shfl_xor_sync(~0u, sum1, 2);
        l0v = l0v * a0 + sum0; l1v = l1v * a1 + sum1;
#pragma unroll
        for (int i = 0; i < 16; i++) {
            O[i][0] *= a0; O[i][1] *= a0; O[i][2] *= a1; O[i][3] *= a1;
        }

        // ---- O += P V (split 3-pass) ----
        const uint32_t vt = stb + vt_rel;
#pragma unroll
        for (int ks = 0; ks < 4; ks++) {
            uint32_t ph[4], pl[4];
            split2(S[2*ks][0],   S[2*ks][1],   ph[0], pl[0]);
            split2(S[2*ks][2],   S[2*ks][3],   ph[1], pl[1]);
            split2(S[2*ks+1][0], S[2*ks+1][1], ph[2], pl[2]);
            split2(S[2*ks+1][2], S[2*ks+1][3], ph[3], pl[3]);
#pragma unroll
            for (int dn = 0; dn < 8; dn++) {
                uint32_t vh[4], vl[4];
                ldsm4t(vh, vt + ks * (16 * ROWB) + dn * 32);
                ldsm4t(vl, vt + KVT + ks * (16 * ROWB) + dn * 32);
                mmabf(O[dn*2],   ph, vh[0], vh[1]);
                mmabf(O[dn*2],   ph, vl[0], vl[1]);
                mmabf(O[dn*2],   pl, vh[0], vh[1]);
                mmabf(O[dn*2+1], ph, vh[2], vh[3]);
                mmabf(O[dn*2+1], ph, vl[2], vl[3]);
                mmabf(O[dn*2+1], pl, vh[2], vh[3]);
            }
        }
        __syncthreads();
    }

    // ---- epilogue ----
    float i0 = 1.f / l0v, i1 = 1.f / l1v;
    long long row0 = (long long)(bb*QL + qt*128 + wid*16 + (lane >> 2)) * 2048 + hh*128;
    int cc = (lane & 3) * 2;
#pragma unroll
    for (int nf = 0; nf < 16; nf++) {
        uint32_t h0, l0, h1, l1;
        split2(O[nf][0] * i0, O[nf][1] * i0, h0, l0);
        split2(O[nf][2] * i1, O[nf][3] * i1, h1, l1);
        long long c0 = row0 + nf*8 + cc;
        *(uint32_t*)(Ohi + c0) = h0;         *(uint32_t*)(Olo + c0) = l0;
        *(uint32_t*)(Ohi + c0 + 8*2048) = h1; *(uint32_t*)(Olo + c0 + 8*2048) = l1;
    }
}

// =================================================================
// launch (ordered so ncu -s 5 -c 1 captures the kv-down hgemm)
// =================================================================
extern "C" void kernel_launch(void* const* d_in, const int* in_sizes, int n_in,
                              void* d_out, int out_size)
{
    const float* x_q       = (const float*)d_in[0];
    const float* x_kv      = (const float*)d_in[1];
    const float* W_dQ      = (const float*)d_in[2];
    const float* q_norm_w  = (const float*)d_in[3];
    const float* W_uQ      = (const float*)d_in[4];
    const float* W_dKV     = (const float*)d_in[5];
    const float* kv_norm_w = (const float*)d_in[6];
    const float* W_ukv     = (const float*)d_in[7];
    const float* W_o       = (const float*)d_in[8];
    float* out = (float*)d_out;

    float *qlat, *ckv;
    cudaGetSymbolAddress((void**)&qlat, g_qlat);
    cudaGetSymbolAddress((void**)&ckv,  g_ckv);
    bf16 *xqh,*xql,*xkvh,*xkvl,*qlh,*qll,*ckvh,*ckvl,*qh,*ql2,*kvh,*kvl,*ath,*atl;
    bf16 *wdqh,*wdql,*wuqh,*wuql,*wdkvh,*wdkvl,*wukvh,*wukvl,*woh,*wol;
    cudaGetSymbolAddress((void**)&xqh,  s_xq_hi);   cudaGetSymbolAddress((void**)&xql,  s_xq_lo);
    cudaGetSymbolAddress((void**)&xkvh, s_xkv_hi);  cudaGetSymbolAddress((void**)&xkvl, s_xkv_lo);
    cudaGetSymbolAddress((void**)&qlh,  s_qlat_hi); cudaGetSymbolAddress((void**)&qll,  s_qlat_lo);
    cudaGetSymbolAddress((void**)&ckvh, s_ckv_hi);  cudaGetSymbolAddress((void**)&ckvl, s_ckv_lo);
    cudaGetSymbolAddress((void**)&qh,   s_q_hi);    cudaGetSymbolAddress((void**)&ql2,  s_q_lo);
    cudaGetSymbolAddress((void**)&kvh,  s_kv_hi);   cudaGetSymbolAddress((void**)&kvl,  s_kv_lo);
    cudaGetSymbolAddress((void**)&ath,  s_attn_hi); cudaGetSymbolAddress((void**)&atl,  s_attn_lo);
    cudaGetSymbolAddress((void**)&wdqh, w_dq_hi);   cudaGetSymbolAddress((void**)&wdql, w_dq_lo);
    cudaGetSymbolAddress((void**)&wuqh, w_uq_hi);   cudaGetSymbolAddress((void**)&wuql, w_uq_lo);
    cudaGetSymbolAddress((void**)&wdkvh, w_dkv_hi); cudaGetSymbolAddress((void**)&wdkvl, w_dkv_lo);
    cudaGetSymbolAddress((void**)&wukvh, w_ukv_hi); cudaGetSymbolAddress((void**)&wukvl, w_ukv_lo);
    cudaGetSymbolAddress((void**)&woh,  w_o_hi);    cudaGetSymbolAddress((void**)&wol,  w_o_lo);

    cudaFuncSetAttribute(hgemm, cudaFuncAttributeMaxDynamicSharedMemorySize, GEMM_SMEM);
    cudaFuncSetAttribute(flash, cudaFuncAttributeMaxDynamicSharedMemorySize, FA_SMEM);

    dim3 tb(32, 8);
    // 0-4: prep needed for kv-down
    split_kernel<<<4096, 256>>>(x_kv, xkvh, xkvl, (long long)BKL*HID/4);
    splitT_kernel<<<dim3(1024/32, HID/32), tb>>>(W_dKV, wdkvh, wdkvl, 1088, HID, 0, 0);
    split_kernel<<<2048, 256>>>(x_q,  xqh,  xql,  (long long)BQL*HID/4);
    splitT_kernel<<<dim3(QLR/32, HID/32), tb>>>(W_dQ,  wdqh,  wdql,  QLR,  HID, 0, 0);
    splitT_kernel<<<dim3(3072/32, QLR/32), tb>>>(W_uQ,  wuqh,  wuql,  3072, QLR, 0, 0);

    // 5: ckv = (x_kv @ W_dKV)[:, :1024]  [8192 x 1024] K=2048  (ncu target)
    hgemm<<<dim3(8, 64), 256, GEMM_SMEM>>>(xkvh, xkvl, HID, wdkvh, wdkvl, HID,
                                           ckv, nullptr, nullptr, GG*LAT, HID, 0, 0, 0);
    // 6: rmsnorm per group + split
    rmsnorm_split<<<dim3(BKL, GG), 256>>>(ckv, kv_norm_w, ckvh, ckvl, LAT, GG*LAT, LAT);
    // 7: W_ukv transpose-split
    splitT_kernel<<<dim3(1024/32, LAT/32, GG), tb>>>(W_ukv, wukvh, wukvl, 1024, LAT,
                                                     (long long)LAT*1024, (long long)1024*LAT);
    // 8: kv[g] = ckv_g @ W_ukv[g]^T   [8192 x 1024] K=256, z=4
    hgemm<<<dim3(8, 64, GG), 256, GEMM_SMEM>>>(ckvh, ckvl, GG*LAT, wukvh, wukvl, LAT,
                                               nullptr, kvh, kvl, 4096, LAT,
                                               (long long)LAT, (long long)1024*LAT, (long long)1024);
    // 9: q_lat = x_q @ W_dQ      [2048 x 512] K=2048
    hgemm<<<dim3(4, 16), 256, GEMM_SMEM>>>(xqh, xql, HID, wdqh, wdql, HID,
                                           qlat, nullptr, nullptr, QLR, HID, 0, 0, 0);
    // 10: rmsnorm + split
    rmsnorm_split<<<dim3(BQL, 1), 256>>>(qlat, q_norm_w, qlh, qll, QLR, QLR, QLR);
    // 11: q = q_lat @ W_uQ       [2048 x 3072] K=512
    hgemm<<<dim3(24, 16), 256, GEMM_SMEM>>>(qlh, qll, QLR, wuqh, wuql, QLR,
                                            nullptr, qh, ql2, 3072, QLR, 0, 0, 0);
    // 12: flash attention
    flash<<<dim3(QL/128, HH, BB), 256, FA_SMEM>>>(qh, ql2, kvh, kvl, ath, atl);
    // 13: W_o transpose-split
    splitT_kernel<<<dim3(HID/32, 2048/32), tb>>>(W_o, woh, wol, HID, 2048, 0, 0);
    // 14: out = attn @ W_o       [2048 x 2048] K=2048
    hgemm<<<dim3(16, 16), 256, GEMM_SMEM>>>(ath, atl, 2048, woh, wol, HID,
                                            out, nullptr, nullptr, HID, 2048, 0, 0, 0);
}

// round 7
// speedup vs baseline: 3.2275x; 1.1723x over previous
#include <cuda_runtime.h>
#include <cuda_bf16.h>
#include <stdint.h>

typedef __nv_bfloat16 bf16;

#define BB 2
#define QL 1024
#define KL 4096
#define HID 2048
#define HH 16
#define HD 128
#define GG 4
#define QLR 512
#define LAT 256
#define BQL (BB*QL)
#define BKL (BB*KL)

__device__ float g_qpart[4 * BQL * QLR];     // split-K partials for q-down
__device__ float g_ckv [BKL * (GG*LAT)];

__device__ bf16 s_xq_hi [BQL*HID],    s_xq_lo [BQL*HID];
__device__ bf16 s_xkv_hi[BKL*HID],    s_xkv_lo[BKL*HID];
__device__ bf16 s_qlat_hi[BQL*QLR],   s_qlat_lo[BQL*QLR];
__device__ bf16 s_ckv_hi[BKL*GG*LAT], s_ckv_lo[BKL*GG*LAT];
__device__ bf16 s_q_hi  [BQL*3072];
__device__ bf16 s_kv_hi [(long long)BKL*4096], s_kv_lo [(long long)BKL*4096];
__device__ bf16 s_attn_hi[BQL*2048],  s_attn_lo[BQL*2048];
__device__ bf16 w_dq_hi [QLR*HID],     w_dq_lo [QLR*HID];
__device__ bf16 w_uq_hi [3072*QLR],    w_uq_lo [3072*QLR];
__device__ bf16 w_dkv_hi[1024*HID],    w_dkv_lo[1024*HID];
__device__ bf16 w_ukv_hi[GG*1024*LAT], w_ukv_lo[GG*1024*LAT];
__device__ bf16 w_o_hi  [HID*2048],    w_o_lo  [HID*2048];

__device__ __forceinline__ uint32_t smem_u32(const void* p) {
    uint32_t a;
    asm("{ .reg .u64 t; cvta.to.shared.u64 t, %1; cvt.u32.u64 %0, t; }" : "=r"(a) : "l"(p));
    return a;
}
__device__ __forceinline__ void cpa16(uint32_t dst, const void* src) {
    asm volatile("cp.async.cg.shared.global [%0], [%1], 16;" :: "r"(dst), "l"(src));
}
#define CP_COMMIT() asm volatile("cp.async.commit_group;")
#define CP_WAIT0()  asm volatile("cp.async.wait_group 0;")
#define CP_WAIT1()  asm volatile("cp.async.wait_group 1;")
#define CP_WAIT2()  asm volatile("cp.async.wait_group 2;")

__device__ __forceinline__ void ldsm4(uint32_t* r, uint32_t a) {
    asm volatile("ldmatrix.sync.aligned.m8n8.x4.shared.b16 {%0,%1,%2,%3}, [%4];"
        : "=r"(r[0]), "=r"(r[1]), "=r"(r[2]), "=r"(r[3]) : "r"(a));
}
__device__ __forceinline__ void ldsm4t(uint32_t* r, uint32_t a) {
    asm volatile("ldmatrix.sync.aligned.m8n8.x4.trans.shared.b16 {%0,%1,%2,%3}, [%4];"
        : "=r"(r[0]), "=r"(r[1]), "=r"(r[2]), "=r"(r[3]) : "r"(a));
}
__device__ __forceinline__ void mmabf(float* c, const uint32_t* a, uint32_t b0, uint32_t b1) {
    asm volatile(
        "mma.sync.aligned.m16n8k16.row.col.f32.bf16.bf16.f32 "
        "{%0,%1,%2,%3}, {%4,%5,%6,%7}, {%8,%9}, {%0,%1,%2,%3};"
        : "+f"(c[0]), "+f"(c[1]), "+f"(c[2]), "+f"(c[3])
        : "r"(a[0]), "r"(a[1]), "r"(a[2]), "r"(a[3]), "r"(b0), "r"(b1));
}
__device__ __forceinline__ void split1(float x, bf16& h, bf16& l) {
    h = __float2bfloat16(x);
    l = __float2bfloat16(x - __bfloat162float(h));
}
__device__ __forceinline__ void split2(float a, float b, uint32_t& hi, uint32_t& lo) {
    bf16 ha, la, hb, lb;
    split1(a, ha, la); split1(b, hb, lb);
    __nv_bfloat162 H = __halves2bfloat162(ha, hb), L = __halves2bfloat162(la, lb);
    hi = *reinterpret_cast<uint32_t*>(&H);
    lo = *reinterpret_cast<uint32_t*>(&L);
}

// ---------------- split kernels ----------------
__global__ void split_kernel(const float* __restrict__ A, bf16* __restrict__ hi,
                             bf16* __restrict__ lo, long long n4)
{
    long long i = blockIdx.x * (long long)blockDim.x + threadIdx.x;
    long long st = (long long)gridDim.x * blockDim.x;
    for (; i < n4; i += st) {
        float4 v = ((const float4*)A)[i];
        uint32_t h0, l0, h1, l1;
        split2(v.x, v.y, h0, l0); split2(v.z, v.w, h1, l1);
        ((uint32_t*)hi)[2*i] = h0; ((uint32_t*)hi)[2*i+1] = h1;
        ((uint32_t*)lo)[2*i] = l0; ((uint32_t*)lo)[2*i+1] = l1;
    }
}

__global__ void splitT_kernel(const float* __restrict__ B, bf16* __restrict__ hiT,
                              bf16* __restrict__ loT, int ldb, int ldt,
                              long long sB, long long sO)
{
    B += blockIdx.z * sB; hiT += blockIdx.z * sO; loT += blockIdx.z * sO;
    __shared__ float t[32][33];
    int tx = threadIdx.x, ty = threadIdx.y;
    int n0 = blockIdx.x * 32, k0 = blockIdx.y * 32;
#pragma unroll
    for (int j = ty; j < 32; j += 8)
        t[j][tx] = B[(long long)(k0 + j) * ldb + n0 + tx];
    __syncthreads();
#pragma unroll
    for (int j = ty; j < 32; j += 8) {
        bf16 h, l;
        split1(t[tx][j], h, l);
        hiT[(long long)(n0 + j) * ldt + k0 + tx] = h;
        loT[(long long)(n0 + j) * ldt + k0 + tx] = l;
    }
}

// ---------------- rmsnorm + split (with split-K partial reduction) ----------------
__global__ void rmsnorm_split(const float* __restrict__ x, const float* __restrict__ w,
                              bf16* __restrict__ hi, bf16* __restrict__ lo,
                              int n, int rowStride, int segStride,
                              int nsplit, long long splitStride)
{
    long long off = (long long)blockIdx.x * rowStride + (long long)blockIdx.y * segStride;
    const float* wp = w + (long long)blockIdx.y * n;
    __shared__ float buf[512];
    __shared__ float red[8]; __shared__ float rs;
    float s = 0.f;
    for (int i = threadIdx.x; i < n; i += 256) {
        float v = 0.f;
        for (int k = 0; k < nsplit; k++) v += x[(long long)k * splitStride + off + i];
        buf[i] = v;
        s += v * v;
    }
#pragma unroll
    for (int o = 16; o; o >>= 1) s += __shfl_xor_sync(~0u, s, o);
    if ((threadIdx.x & 31) == 0) red[threadIdx.x >> 5] = s;
    __syncthreads();
    if (threadIdx.x == 0) {
        float t = 0.f;
#pragma unroll
        for (int i = 0; i < 8; i++) t += red[i];
        rs = rsqrtf(t / (float)n + 1e-6f);
    }
    __syncthreads();
    float r = rs;
    for (int i = threadIdx.x; i < n; i += 256) {
        bf16 h, l;
        split1(buf[i] * r * wp[i], h, l);
        hi[off + i] = h; lo[off + i] = l;
    }
}

// =================================================================
// split-bf16 HMMA GEMM: C[M,N] = A[M,K] * B[N,K]^T
// 128x128 tile, BK=32, 256 thr (8 warps 2x4), 2 CTAs/SM
// kvmode: store Clo only for V columns ((col>>7)&1)
// =================================================================
#define GR 80
#define GT (128*GR)
#define GSTG (4*GT)
#define GEMM_SMEM (2*GSTG)

#define GLOAD(stg, k0) do {                                   \
    uint32_t _d = (stg) + sro;                                \
    _Pragma("unroll")                                         \
    for (int _j = 0; _j < 2; _j++) {                          \
        int _e = lc * 16 + _j * 8;                            \
        cpa16(_d + _j*16,        gAh + (k0) + _e);            \
        cpa16(_d + GT + _j*16,   gAl + (k0) + _e);            \
        cpa16(_d + 2*GT + _j*16, gBh + (k0) + _e);            \
        cpa16(_d + 3*GT + _j*16, gBl + (k0) + _e);            \
    }                                                         \
} while (0)

__global__ __launch_bounds__(256, 2) void hgemm(
    const bf16* __restrict__ Ah, const bf16* __restrict__ Al, int lda,
    const bf16* __restrict__ Bh, const bf16* __restrict__ Bl, int ldb,
    float* Cf, bf16* Chi, bf16* Clo, int ldc, int K,
    long long sAz, long long sBz, long long sCz, int kvmode)
{
    extern __shared__ char smc[];
    const uint32_t sb = smem_u32(smc);
    const int tid = threadIdx.x, lane = tid & 31, wid = tid >> 5;
    const int m0 = blockIdx.y * 128, n0 = blockIdx.x * 128;
    const int wm = wid >> 2, wn = wid & 3;

    Ah += blockIdx.z * sAz;  Al += blockIdx.z * sAz;
    Bh += blockIdx.z * sBz;  Bl += blockIdx.z * sBz;
    long long coff = blockIdx.z * sCz;

    const int lrow = tid >> 1, lc = tid & 1;
    const bf16* gAh = Ah + (long long)(m0 + lrow) * lda;
    const bf16* gAl = Al + (long long)(m0 + lrow) * lda;
    const bf16* gBh = Bh + (long long)(n0 + lrow) * ldb;
    const bf16* gBl = Bl + (long long)(n0 + lrow) * ldb;
    const uint32_t sro = sb + lrow * GR + lc * 32;

    float acc[4][4][4];
#pragma unroll
    for (int i = 0; i < 4; i++)
#pragma unroll
        for (int j = 0; j < 4; j++)
#pragma unroll
            for (int k = 0; k < 4; k++) acc[i][j][k] = 0.f;

    const uint32_t a_base = sb + (wm * 64 + (lane & 15)) * GR + (lane >> 4) * 16;
    const uint32_t b_base = sb + 2 * GT +
        (wn * 32 + (lane & 7) + ((lane >> 4) << 3)) * GR + ((lane >> 3) & 1) * 16;

    const int nIter = K >> 5;
    GLOAD(0, 0);
    CP_COMMIT();

#pragma unroll 1
    for (int it = 0; it < nIter; it++) {
        const int s = it & 1;
        if (it + 1 < nIter) { GLOAD(((it + 1) & 1) * GSTG, (it + 1) << 5); CP_COMMIT(); CP_WAIT1(); }
        else CP_WAIT0();
        __syncthreads();

        const uint32_t ab = a_base + s * GSTG;
        const uint32_t bb = b_base + s * GSTG;
#pragma unroll
        for (int s2 = 0; s2 < 2; s2++) {
            uint32_t ah[4][4], al[4][4], bh[4][2], bl[4][2];
#pragma unroll
            for (int mt = 0; mt < 4; mt++) {
                ldsm4(ah[mt], ab + s2 * 32 + mt * (16 * GR));
                ldsm4(al[mt], ab + GT + s2 * 32 + mt * (16 * GR));
            }
#pragma unroll
            for (int np = 0; np < 2; np++) {
                uint32_t t[4];
                ldsm4(t, bb + s2 * 32 + np * (16 * GR));
                bh[np*2][0] = t[0]; bh[np*2][1] = t[1];
                bh[np*2+1][0] = t[2]; bh[np*2+1][1] = t[3];
                ldsm4(t, bb + GT + s2 * 32 + np * (16 * GR));
                bl[np*2][0] = t[0]; bl[np*2][1] = t[1];
                bl[np*2+1][0] = t[2]; bl[np*2+1][1] = t[3];
            }
#pragma unroll
            for (int mt = 0; mt < 4; mt++)
#pragma unroll
                for (int nf = 0; nf < 4; nf++) {
                    mmabf(acc[mt][nf], ah[mt], bh[nf][0], bh[nf][1]);
                    mmabf(acc[mt][nf], ah[mt], bl[nf][0], bl[nf][1]);
                    mmabf(acc[mt][nf], al[mt], bh[nf][0], bh[nf][1]);
                }
        }
        __syncthreads();
    }

#pragma unroll
    for (int mt = 0; mt < 4; mt++)
#pragma unroll
        for (int nf = 0; nf < 4; nf++) {
            long long row = m0 + wm * 64 + mt * 16 + (lane >> 2);
            int col = n0 + wn * 32 + nf * 8 + (lane & 3) * 2;
            const float* c = acc[mt][nf];
            if (Cf) {
                float* p = Cf + coff;
                *(float2*)(p + row * ldc + col) = make_float2(c[0], c[1]);
                *(float2*)(p + (row + 8) * ldc + col) = make_float2(c[2], c[3]);
            }
            if (Chi) {
                uint32_t h0, l0, h1, l1;
                split2(c[0], c[1], h0, l0);
                split2(c[2], c[3], h1, l1);
                *(uint32_t*)(Chi + coff + row * ldc + col) = h0;
                *(uint32_t*)(Chi + coff + (row + 8) * ldc + col) = h1;
                bool sl = (Clo != nullptr) && (!kvmode || ((col >> 7) & 1));
                if (sl) {
                    *(uint32_t*)(Clo + coff + row * ldc + col) = l0;
                    *(uint32_t*)(Clo + coff + (row + 8) * ldc + col) = l1;
                }
            }
        }
}

// =================================================================
// HMMA flash attention: BM=128, BN=64, 8 warps
// QK plain bf16 1-pass; PV split-bf16 3-pass. Q frags in registers.
// smem: Qh [QT] + 3 stages of {Kh, Vh, Vl} [3*KVT each]
// =================================================================
#define ROWB 272
#define QT   (128*ROWB)        // 34816
#define KVT  (64*ROWB)         // 17408
#define KV3  (3*KVT)           // 52224
#define FA_SMEM (QT + 3*KV3)   // 191488
#define SCL 0.1275174313213403f  // 1/sqrt(128) * log2(e)
#define NIT (KL/64)

#define KVLOAD(stb, jb) do {                                                   \
    long long rg = ((long long)(bb*KL + (jb)*64 + kr)) * 4096 + hh*256 + kq*32; \
    uint32_t d = (stb) + kr * ROWB + kq * 64;                                  \
    _Pragma("unroll")                                                          \
    for (int _j = 0; _j < 4; _j++) {                                           \
        cpa16(d + _j*16,          KVh + rg + _j*8);                            \
        cpa16(d + KVT + _j*16,    KVh + rg + 128 + _j*8);                      \
        cpa16(d + 2*KVT + _j*16,  KVl + rg + 128 + _j*8);                      \
    }                                                                          \
} while (0)

__global__ __launch_bounds__(256, 1) void flash(
    const bf16* __restrict__ Qh,
    const bf16* __restrict__ KVh, const bf16* __restrict__ KVl,
    bf16* __restrict__ Ohi, bf16* __restrict__ Olo)
{
    extern __shared__ char smc[];
    const uint32_t sb = smem_u32(smc);
    const uint32_t kv0 = sb + QT;
    const int tid = threadIdx.x, lane = tid & 31, wid = tid >> 5;
    const int qt = blockIdx.x, hh = blockIdx.y, bb = blockIdx.z;
    const int kr = tid >> 2, kq = tid & 3;

    // Q (hi only): 128 rows x 256B
    {
        int r = tid >> 1, hc = tid & 1;
        long long rg = ((long long)(bb*QL + qt*128 + r)) * 3072 + hh*192 + hc*64;
        uint32_t d = sb + r * ROWB + hc * 128;
#pragma unroll
        for (int j = 0; j < 8; j++) cpa16(d + j*16, Qh + rg + j*8);
    }
    CP_COMMIT();
    KVLOAD(kv0, 0);            CP_COMMIT();
    KVLOAD(kv0 + KV3, 1);      CP_COMMIT();

    float O[16][4];
#pragma unroll
    for (int i = 0; i < 16; i++)
#pragma unroll
        for (int j = 0; j < 4; j++) O[i][j] = 0.f;
    float m0v = -1e30f, m1v = -1e30f, l0v = 0.f, l1v = 0.f;

    const uint32_t a_q = sb + (wid * 16 + (lane & 15)) * ROWB + (lane >> 4) * 16;
    const uint32_t bk_rel = ((lane & 7) + ((lane >> 4) << 3)) * ROWB + ((lane >> 3) & 1) * 16;
    const uint32_t vt_rel = KVT + (lane & 15) * ROWB + ((lane >> 4) << 4);

    // hoist Q fragments (Q group completes once <=2 groups pending)
    CP_WAIT2();
    __syncthreads();
    uint32_t qfh[8][4];
#pragma unroll
    for (int d16 = 0; d16 < 8; d16++) ldsm4(qfh[d16], a_q + d16 * 32);

#pragma unroll 1
    for (int jb = 0; jb < NIT; jb++) {
        const uint32_t stb = kv0 + (jb % 3) * KV3;
        if (jb + 2 < NIT) { KVLOAD(kv0 + ((jb + 2) % 3) * KV3, jb + 2); CP_COMMIT(); }
        if (jb < NIT - 2) CP_WAIT2();
        else if (jb == NIT - 2) CP_WAIT1();
        else CP_WAIT0();
        __syncthreads();

        // ---- S = Qh Kh^T (1-pass bf16) ----
        float S[8][4];
#pragma unroll
        for (int f = 0; f < 8; f++)
#pragma unroll
            for (int e = 0; e < 4; e++) S[f][e] = 0.f;

        const uint32_t bk = stb + bk_rel;
#pragma unroll
        for (int d16 = 0; d16 < 8; d16++) {
#pragma unroll
            for (int np = 0; np < 4; np++) {
                uint32_t kh4[4];
                ldsm4(kh4, bk + np * (16 * ROWB) + d16 * 32);
                mmabf(S[np*2],   qfh[d16], kh4[0], kh4[1]);
                mmabf(S[np*2+1], qfh[d16], kh4[2], kh4[3]);
            }
        }

        // ---- online softmax ----
        float mloc0 = -1e30f, mloc1 = -1e30f;
#pragma unroll
        for (int f = 0; f < 8; f++) {
            S[f][0] *= SCL; S[f][1] *= SCL; S[f][2] *= SCL; S[f][3] *= SCL;
            mloc0 = fmaxf(mloc0, fmaxf(S[f][0], S[f][1]));
            mloc1 = fmaxf(mloc1, fmaxf(S[f][2], S[f][3]));
        }
        mloc0 = fmaxf(mloc0, __shfl_xor_sync(~0u, mloc0, 1));
        mloc0 = fmaxf(mloc0, __shfl_xor_sync(~0u, mloc0, 2));
        mloc1 = fmaxf(mloc1, __shfl_xor_sync(~0u, mloc1, 1));
        mloc1 = fmaxf(mloc1, __shfl_xor_sync(~0u, mloc1, 2));
        float mn0 = fmaxf(m0v, mloc0), mn1 = fmaxf(m1v, mloc1);
        float a0 = exp2f(m0v - mn0), a1 = exp2f(m1v - mn1);
        m0v = mn0; m1v = mn1;
        float sum0 = 0.f, sum1 = 0.f;
#pragma unroll
        for (int f = 0; f < 8; f++) {
            S[f][0] = exp2f(S[f][0] - mn0); S[f][1] = exp2f(S[f][1] - mn0);
            S[f][2] = exp2f(S[f][2] - mn1); S[f][3] = exp2f(S[f][3] - mn1);
            sum0 += S[f][0] + S[f][1];
            sum1 += S[f][2] + S[f][3];
        }
        sum0 += __shfl_xor_sync(~0u, sum0, 1); sum0 += __shfl_xor_sync(~0u, sum0, 2);
        sum1 += __shfl_xor_sync(~0u, sum1, 1); sum1 += __shfl_xor_sync(~0u, sum1, 2);
        l0v = l0v * a0 + sum0; l1v = l1v * a1 + sum1;
#pragma unroll
        for (int i = 0; i < 16; i++) {
            O[i][0] *= a0; O[i][1] *= a0; O[i][2] *= a1; O[i][3] *= a1;
        }

        // ---- O += P V (split 3-pass) ----
        const uint32_t vt = stb + vt_rel;
#pragma unroll
        for (int ks = 0; ks < 4; ks++) {
            uint32_t ph[4], pl[4];
            split2(S[2*ks][0],   S[2*ks][1],   ph[0], pl[0]);
            split2(S[2*ks][2],   S[2*ks][3],   ph[1], pl[1]);
            split2(S[2*ks+1][0], S[2*ks+1][1], ph[2], pl[2]);
            split2(S[2*ks+1][2], S[2*ks+1][3], ph[3], pl[3]);
#pragma unroll
            for (int dn = 0; dn < 8; dn++) {
                uint32_t vh[4], vl[4];
                ldsm4t(vh, vt + ks * (16 * ROWB) + dn * 32);
                ldsm4t(vl, vt + KVT + ks * (16 * ROWB) + dn * 32);
                mmabf(O[dn*2],   ph, vh[0], vh[1]);
                mmabf(O[dn*2],   ph, vl[0], vl[1]);
                mmabf(O[dn*2],   pl, vh[0], vh[1]);
                mmabf(O[dn*2+1], ph, vh[2], vh[3]);
                mmabf(O[dn*2+1], ph, vl[2], vl[3]);
                mmabf(O[dn*2+1], pl, vh[2], vh[3]);
            }
        }
        __syncthreads();
    }

    // ---- epilogue ----
    float i0 = 1.f / l0v, i1 = 1.f / l1v;
    long long row0 = (long long)(bb*QL + qt*128 + wid*16 + (lane >> 2)) * 2048 + hh*128;
    int cc = (lane & 3) * 2;
#pragma unroll
    for (int nf = 0; nf < 16; nf++) {
        uint32_t h0, l0, h1, l1;
        split2(O[nf][0] * i0, O[nf][1] * i0, h0, l0);
        split2(O[nf][2] * i1, O[nf][3] * i1, h1, l1);
        long long c0 = row0 + nf*8 + cc;
        *(uint32_t*)(Ohi + c0) = h0;         *(uint32_t*)(Olo + c0) = l0;
        *(uint32_t*)(Ohi + c0 + 8*2048) = h1; *(uint32_t*)(Olo + c0 + 8*2048) = l1;
    }
}

// =================================================================
// launch (kv-down hgemm placed at launch index 3 for ncu capture)
// =================================================================
extern "C" void kernel_launch(void* const* d_in, const int* in_sizes, int n_in,
                              void* d_out, int out_size)
{
    const float* x_q       = (const float*)d_in[0];
    const float* x_kv      = (const float*)d_in[1];
    const float* W_dQ      = (const float*)d_in[2];
    const float* q_norm_w  = (const float*)d_in[3];
    const float* W_uQ      = (const float*)d_in[4];
    const float* W_dKV     = (const float*)d_in[5];
    const float* kv_norm_w = (const float*)d_in[6];
    const float* W_ukv     = (const float*)d_in[7];
    const float* W_o       = (const float*)d_in[8];
    float* out = (float*)d_out;

    float *qpart, *ckv;
    cudaGetSymbolAddress((void**)&qpart, g_qpart);
    cudaGetSymbolAddress((void**)&ckv,  g_ckv);
    bf16 *xqh,*xql,*xkvh,*xkvl,*qlh,*qll,*ckvh,*ckvl,*qh,*kvh,*kvl,*ath,*atl;
    bf16 *wdqh,*wdql,*wuqh,*wuql,*wdkvh,*wdkvl,*wukvh,*wukvl,*woh,*wol;
    cudaGetSymbolAddress((void**)&xqh,  s_xq_hi);   cudaGetSymbolAddress((void**)&xql,  s_xq_lo);
    cudaGetSymbolAddress((void**)&xkvh, s_xkv_hi);  cudaGetSymbolAddress((void**)&xkvl, s_xkv_lo);
    cudaGetSymbolAddress((void**)&qlh,  s_qlat_hi); cudaGetSymbolAddress((void**)&qll,  s_qlat_lo);
    cudaGetSymbolAddress((void**)&ckvh, s_ckv_hi);  cudaGetSymbolAddress((void**)&ckvl, s_ckv_lo);
    cudaGetSymbolAddress((void**)&qh,   s_q_hi);
    cudaGetSymbolAddress((void**)&kvh,  s_kv_hi);   cudaGetSymbolAddress((void**)&kvl,  s_kv_lo);
    cudaGetSymbolAddress((void**)&ath,  s_attn_hi); cudaGetSymbolAddress((void**)&atl,  s_attn_lo);
    cudaGetSymbolAddress((void**)&wdqh, w_dq_hi);   cudaGetSymbolAddress((void**)&wdql, w_dq_lo);
    cudaGetSymbolAddress((void**)&wuqh, w_uq_hi);   cudaGetSymbolAddress((void**)&wuql, w_uq_lo);
    cudaGetSymbolAddress((void**)&wdkvh, w_dkv_hi); cudaGetSymbolAddress((void**)&wdkvl, w_dkv_lo);
    cudaGetSymbolAddress((void**)&wukvh, w_ukv_hi); cudaGetSymbolAddress((void**)&wukvl, w_ukv_lo);
    cudaGetSymbolAddress((void**)&woh,  w_o_hi);    cudaGetSymbolAddress((void**)&wol,  w_o_lo);

    cudaFuncSetAttribute(hgemm, cudaFuncAttributeMaxDynamicSharedMemorySize, GEMM_SMEM);
    cudaFuncSetAttribute(flash, cudaFuncAttributeMaxDynamicSharedMemorySize, FA_SMEM);

    dim3 tb(32, 8);
    // 0-2: prep for kv-down
    split_kernel<<<4096, 256>>>(x_kv, xkvh, xkvl, (long long)BKL*HID/4);
    splitT_kernel<<<dim3(1024/32, HID/32), tb>>>(W_dKV, wdkvh, wdkvl, 1088, HID, 0, 0);
    split_kernel<<<2048, 256>>>(x_q,  xqh,  xql,  (long long)BQL*HID/4);

    // 3: ckv = (x_kv @ W_dKV)[:, :1024]  [8192 x 1024] K=2048  (ncu target)
    hgemm<<<dim3(8, 64), 256, GEMM_SMEM>>>(xkvh, xkvl, HID, wdkvh, wdkvl, HID,
                                           ckv, nullptr, nullptr, GG*LAT, HID, 0, 0, 0, 0);
    // 4: rmsnorm per group + split
    rmsnorm_split<<<dim3(BKL, GG), 256>>>(ckv, kv_norm_w, ckvh, ckvl, LAT, GG*LAT, LAT, 1, 0);
    // 5: W_ukv transpose-split
    splitT_kernel<<<dim3(1024/32, LAT/32, GG), tb>>>(W_ukv, wukvh, wukvl, 1024, LAT,
                                                     (long long)LAT*1024, (long long)1024*LAT);
    // 6: kv[g] = ckv_g @ W_ukv[g]^T  [8192 x 1024] K=256, z=4; K-cols hi-only
    hgemm<<<dim3(8, 64, GG), 256, GEMM_SMEM>>>(ckvh, ckvl, GG*LAT, wukvh, wukvl, LAT,
                                               nullptr, kvh, kvl, 4096, LAT,
                                               (long long)LAT, (long long)1024*LAT, (long long)1024, 1);
    // 7: W_dQ transpose-split
    splitT_kernel<<<dim3(QLR/32, HID/32), tb>>>(W_dQ, wdqh, wdql, QLR, HID, 0, 0);
    // 8: q_lat partials = x_q @ W_dQ, split-K=4 (z = k-chunk of 512)
    hgemm<<<dim3(4, 16, 4), 256, GEMM_SMEM>>>(xqh, xql, HID, wdqh, wdql, HID,
                                              qpart, nullptr, nullptr, QLR, 512,
                                              512, 512, (long long)BQL*QLR, 0);
    // 9: reduce partials + rmsnorm + split
    rmsnorm_split<<<dim3(BQL, 1), 256>>>(qpart, q_norm_w, qlh, qll, QLR, QLR, QLR,
                                         4, (long long)BQL*QLR);
    // 10: W_uQ transpose-split
    splitT_kernel<<<dim3(3072/32, QLR/32), tb>>>(W_uQ, wuqh, wuql, 3072, QLR, 0, 0);
    // 11: q = q_lat @ W_uQ  [2048 x 3072] K=512, hi only
    hgemm<<<dim3(24, 16), 256, GEMM_SMEM>>>(qlh, qll, QLR, wuqh, wuql, QLR,
                                            nullptr, qh, nullptr, 3072, QLR, 0, 0, 0, 0);
    // 12: flash attention
    flash<<<dim3(QL/128, HH, BB), 256, FA_SMEM>>>(qh, kvh, kvl, ath, atl);
    // 13: W_o transpose-split
    splitT_kernel<<<dim3(HID/32, 2048/32), tb>>>(W_o, woh, wol, HID, 2048, 0, 0);
    // 14: out = attn @ W_o  [2048 x 2048] K=2048
    hgemm<<<dim3(16, 16), 256, GEMM_SMEM>>>(ath, atl, 2048, woh, wol, HID,
                                            out, nullptr, nullptr, HID, 2048, 0, 0, 0, 0);
}

// round 8
// speedup vs baseline: 3.4415x; 1.0663x over previous
#include <cuda_runtime.h>
#include <cuda_bf16.h>
#include <cuda_fp16.h>
#include <stdint.h>

typedef __nv_bfloat16 bf16;

#define BB 2
#define QL 1024
#define KL 4096
#define HID 2048
#define HH 16
#define HD 128
#define GG 4
#define QLR 512
#define LAT 256
#define BQL (BB*QL)
#define BKL (BB*KL)

__device__ float g_qpart[4 * BQL * QLR];
__device__ float g_ckv [BKL * (GG*LAT)];

__device__ bf16 s_xq_hi [BQL*HID],    s_xq_lo [BQL*HID];
__device__ bf16 s_xkv_hi[BKL*HID],    s_xkv_lo[BKL*HID];
__device__ bf16 s_qlat_hi[BQL*QLR],   s_qlat_lo[BQL*QLR];
__device__ bf16 s_ckv_hi[BKL*GG*LAT], s_ckv_lo[BKL*GG*LAT];
__device__ bf16 s_q_hi  [BQL*3072];                                  // fp16 payload
__device__ bf16 s_kv_hi [(long long)BKL*4096], s_kv_lo [(long long)BKL*4096]; // K cols fp16, V cols bf16
__device__ bf16 s_attn_hi[BQL*2048],  s_attn_lo[BQL*2048];
__device__ bf16 w_dq_hi [QLR*HID],     w_dq_lo [QLR*HID];
__device__ bf16 w_uq_hi [3072*QLR],    w_uq_lo [3072*QLR];
__device__ bf16 w_dkv_hi[1024*HID],    w_dkv_lo[1024*HID];
__device__ bf16 w_ukv_hi[GG*1024*LAT], w_ukv_lo[GG*1024*LAT];
__device__ bf16 w_o_hi  [HID*2048],    w_o_lo  [HID*2048];

__device__ __forceinline__ uint32_t smem_u32(const void* p) {
    uint32_t a;
    asm("{ .reg .u64 t; cvta.to.shared.u64 t, %1; cvt.u32.u64 %0, t; }" : "=r"(a) : "l"(p));
    return a;
}
__device__ __forceinline__ void cpa16(uint32_t dst, const void* src) {
    asm volatile("cp.async.cg.shared.global [%0], [%1], 16;" :: "r"(dst), "l"(src));
}
#define CP_COMMIT() asm volatile("cp.async.commit_group;")
#define CP_WAIT0()  asm volatile("cp.async.wait_group 0;")
#define CP_WAIT1()  asm volatile("cp.async.wait_group 1;")
#define CP_WAIT2()  asm volatile("cp.async.wait_group 2;")

__device__ __forceinline__ void ldsm4(uint32_t* r, uint32_t a) {
    asm volatile("ldmatrix.sync.aligned.m8n8.x4.shared.b16 {%0,%1,%2,%3}, [%4];"
        : "=r"(r[0]), "=r"(r[1]), "=r"(r[2]), "=r"(r[3]) : "r"(a));
}
__device__ __forceinline__ void ldsm4t(uint32_t* r, uint32_t a) {
    asm volatile("ldmatrix.sync.aligned.m8n8.x4.trans.shared.b16 {%0,%1,%2,%3}, [%4];"
        : "=r"(r[0]), "=r"(r[1]), "=r"(r[2]), "=r"(r[3]) : "r"(a));
}
__device__ __forceinline__ void mmabf(float* c, const uint32_t* a, uint32_t b0, uint32_t b1) {
    asm volatile(
        "mma.sync.aligned.m16n8k16.row.col.f32.bf16.bf16.f32 "
        "{%0,%1,%2,%3}, {%4,%5,%6,%7}, {%8,%9}, {%0,%1,%2,%3};"
        : "+f"(c[0]), "+f"(c[1]), "+f"(c[2]), "+f"(c[3])
        : "r"(a[0]), "r"(a[1]), "r"(a[2]), "r"(a[3]), "r"(b0), "r"(b1));
}
__device__ __forceinline__ void mmafp(float* c, const uint32_t* a, uint32_t b0, uint32_t b1) {
    asm volatile(
        "mma.sync.aligned.m16n8k16.row.col.f32.f16.f16.f32 "
        "{%0,%1,%2,%3}, {%4,%5,%6,%7}, {%8,%9}, {%0,%1,%2,%3};"
        : "+f"(c[0]), "+f"(c[1]), "+f"(c[2]), "+f"(c[3])
        : "r"(a[0]), "r"(a[1]), "r"(a[2]), "r"(a[3]), "r"(b0), "r"(b1));
}
__device__ __forceinline__ void split1(float x, bf16& h, bf16& l) {
    h = __float2bfloat16(x);
    l = __float2bfloat16(x - __bfloat162float(h));
}
__device__ __forceinline__ void split2(float a, float b, uint32_t& hi, uint32_t& lo) {
    bf16 ha, la, hb, lb;
    split1(a, ha, la); split1(b, hb, lb);
    __nv_bfloat162 H = __halves2bfloat162(ha, hb), L = __halves2bfloat162(la, lb);
    hi = *reinterpret_cast<uint32_t*>(&H);
    lo = *reinterpret_cast<uint32_t*>(&L);
}
__device__ __forceinline__ uint32_t packh2(float a, float b) {
    __half2 h = __floats2half2_rn(a, b);
    return *reinterpret_cast<uint32_t*>(&h);
}

// ---------------- split kernels ----------------
__global__ void split_kernel(const float* __restrict__ A, bf16* __restrict__ hi,
                             bf16* __restrict__ lo, long long n4)
{
    long long i = blockIdx.x * (long long)blockDim.x + threadIdx.x;
    long long st = (long long)gridDim.x * blockDim.x;
    for (; i < n4; i += st) {
        float4 v = ((const float4*)A)[i];
        uint32_t h0, l0, h1, l1;
        split2(v.x, v.y, h0, l0); split2(v.z, v.w, h1, l1);
        ((uint32_t*)hi)[2*i] = h0; ((uint32_t*)hi)[2*i+1] = h1;
        ((uint32_t*)lo)[2*i] = l0; ((uint32_t*)lo)[2*i+1] = l1;
    }
}

__global__ void splitT_kernel(const float* __restrict__ B, bf16* __restrict__ hiT,
                              bf16* __restrict__ loT, int ldb, int ldt,
                              long long sB, long long sO)
{
    B += blockIdx.z * sB; hiT += blockIdx.z * sO; loT += blockIdx.z * sO;
    __shared__ float t[32][33];
    int tx = threadIdx.x, ty = threadIdx.y;
    int n0 = blockIdx.x * 32, k0 = blockIdx.y * 32;
#pragma unroll
    for (int j = ty; j < 32; j += 8)
        t[j][tx] = B[(long long)(k0 + j) * ldb + n0 + tx];
    __syncthreads();
#pragma unroll
    for (int j = ty; j < 32; j += 8) {
        bf16 h, l;
        split1(t[tx][j], h, l);
        hiT[(long long)(n0 + j) * ldt + k0 + tx] = h;
        loT[(long long)(n0 + j) * ldt + k0 + tx] = l;
    }
}

// ---------------- rmsnorm + split (with split-K partial reduction) ----------------
__global__ void rmsnorm_split(const float* __restrict__ x, const float* __restrict__ w,
                              bf16* __restrict__ hi, bf16* __restrict__ lo,
                              int n, int rowStride, int segStride,
                              int nsplit, long long splitStride)
{
    long long off = (long long)blockIdx.x * rowStride + (long long)blockIdx.y * segStride;
    const float* wp = w + (long long)blockIdx.y * n;
    __shared__ float buf[512];
    __shared__ float red[8]; __shared__ float rs;
    float s = 0.f;
    for (int i = threadIdx.x; i < n; i += 256) {
        float v = 0.f;
        for (int k = 0; k < nsplit; k++) v += x[(long long)k * splitStride + off + i];
        buf[i] = v;
        s += v * v;
    }
#pragma unroll
    for (int o = 16; o; o >>= 1) s += __shfl_xor_sync(~0u, s, o);
    if ((threadIdx.x & 31) == 0) red[threadIdx.x >> 5] = s;
    __syncthreads();
    if (threadIdx.x == 0) {
        float t = 0.f;
#pragma unroll
        for (int i = 0; i < 8; i++) t += red[i];
        rs = rsqrtf(t / (float)n + 1e-6f);
    }
    __syncthreads();
    float r = rs;
    for (int i = threadIdx.x; i < n; i += 256) {
        bf16 h, l;
        split1(buf[i] * r * wp[i], h, l);
        hi[off + i] = h; lo[off + i] = l;
    }
}

// =================================================================
// split-bf16 HMMA GEMM: C[M,N] = A[M,K] * B[N,K]^T
// 128x128 tile, BK=32, 8 warps, XOR-swizzled 64B rows,
// 3-stage cp.async pipeline, one barrier per K-step, 2 CTAs/SM.
// mode: 0=fp32 Cf; 1=bf16 hi/lo; 2=kv (K fp16, V bf16 hi/lo); 3=fp16
// =================================================================
#define GT   8192            // one 128x32 bf16 tile (64B rows)
#define GSTG (4*GT)          // Ah|Al|Bh|Bl
#define GEMM_SMEM (3*GSTG)   // 98304

#define GLOAD(stg, k0) do {                                         \
    _Pragma("unroll")                                               \
    for (int _j = 0; _j < 2; _j++) {                                \
        int _c = lc * 2 + _j;                                       \
        uint32_t _d = (stg) + soff[_j];                             \
        cpa16(_d,          gAh + (k0) + _c * 8);                    \
        cpa16(_d + GT,     gAl + (k0) + _c * 8);                    \
        cpa16(_d + 2*GT,   gBh + (k0) + _c * 8);                    \
        cpa16(_d + 3*GT,   gBl + (k0) + _c * 8);                    \
    }                                                               \
} while (0)

__global__ __launch_bounds__(256, 2) void hgemm(
    const bf16* __restrict__ Ah, const bf16* __restrict__ Al, int lda,
    const bf16* __restrict__ Bh, const bf16* __restrict__ Bl, int ldb,
    float* Cf, bf16* Chi, bf16* Clo, int ldc, int K,
    long long sAz, long long sBz, long long sCz, int mode)
{
    extern __shared__ char smc[];
    const uint32_t sb = smem_u32(smc);
    const int tid = threadIdx.x, lane = tid & 31, wid = tid >> 5;
    const int m0 = blockIdx.y * 128, n0 = blockIdx.x * 128;
    const int wm = wid >> 2, wn = wid & 3;

    Ah += blockIdx.z * sAz;  Al += blockIdx.z * sAz;
    Bh += blockIdx.z * sBz;  Bl += blockIdx.z * sBz;
    long long coff = blockIdx.z * sCz;

    const int lrow = tid >> 1, lc = tid & 1;
    const int lsw = (lrow >> 1) & 3;
    const bf16* gAh = Ah + (long long)(m0 + lrow) * lda;
    const bf16* gAl = Al + (long long)(m0 + lrow) * lda;
    const bf16* gBh = Bh + (long long)(n0 + lrow) * ldb;
    const bf16* gBl = Bl + (long long)(n0 + lrow) * ldb;
    uint32_t soff[2];
    soff[0] = lrow * 64 + (((lc * 2 + 0) ^ lsw) * 16);
    soff[1] = lrow * 64 + (((lc * 2 + 1) ^ lsw) * 16);

    float acc[4][4][4];
#pragma unroll
    for (int i = 0; i < 4; i++)
#pragma unroll
        for (int j = 0; j < 4; j++)
#pragma unroll
            for (int k = 0; k < 4; k++) acc[i][j][k] = 0.f;

    // fragment address precompute (swizzle-aware)
    const int rlA = lane & 15, swA = (rlA >> 1) & 3, cAhi = lane >> 4;
    const uint32_t aRel = (wm * 64 + rlA) * 64;
    uint32_t aOff[2] = { (uint32_t)(((0 + cAhi) ^ swA) * 16),
                         (uint32_t)(((2 + cAhi) ^ swA) * 16) };
    const int rlB = (lane & 7) | ((lane >> 4) << 3), swB = (rlB >> 1) & 3, cB = (lane >> 3) & 1;
    const uint32_t bRel = 2 * GT + (wn * 32 + rlB) * 64;
    uint32_t bOff[2] = { (uint32_t)(((0 + cB) ^ swB) * 16),
                         (uint32_t)(((2 + cB) ^ swB) * 16) };

    const int nIter = K >> 5;
    GLOAD(sb, 0);           CP_COMMIT();
    GLOAD(sb + GSTG, 32);   CP_COMMIT();

#pragma unroll 1
    for (int it = 0; it < nIter; it++) {
        if (it + 1 < nIter) CP_WAIT1();
        else                CP_WAIT0();
        __syncthreads();
        if (it + 2 < nIter) { GLOAD(sb + ((it + 2) % 3) * GSTG, (it + 2) << 5); CP_COMMIT(); }

        const uint32_t stg = sb + (it % 3) * GSTG;
#pragma unroll
        for (int s2 = 0; s2 < 2; s2++) {
            uint32_t ah[4][4], al[4][4], bh[4][2], bl[4][2];
#pragma unroll
            for (int mt = 0; mt < 4; mt++) {
                ldsm4(ah[mt], stg + aRel + mt * 1024 + aOff[s2]);
                ldsm4(al[mt], stg + GT + aRel + mt * 1024 + aOff[s2]);
            }
#pragma unroll
            for (int np = 0; np < 2; np++) {
                uint32_t t[4];
                ldsm4(t, stg + bRel + np * 1024 + bOff[s2]);
                bh[np*2][0] = t[0]; bh[np*2][1] = t[1];
                bh[np*2+1][0] = t[2]; bh[np*2+1][1] = t[3];
                ldsm4(t, stg + GT + bRel + np * 1024 + bOff[s2]);
                bl[np*2][0] = t[0]; bl[np*2][1] = t[1];
                bl[np*2+1][0] = t[2]; bl[np*2+1][1] = t[3];
            }
#pragma unroll
            for (int mt = 0; mt < 4; mt++)
#pragma unroll
                for (int nf = 0; nf < 4; nf++) {
                    mmabf(acc[mt][nf], ah[mt], bh[nf][0], bh[nf][1]);
                    mmabf(acc[mt][nf], ah[mt], bl[nf][0], bl[nf][1]);
                    mmabf(acc[mt][nf], al[mt], bh[nf][0], bh[nf][1]);
                }
        }
    }

#pragma unroll
    for (int mt = 0; mt < 4; mt++)
#pragma unroll
        for (int nf = 0; nf < 4; nf++) {
            long long row = m0 + wm * 64 + mt * 16 + (lane >> 2);
            int col = n0 + wn * 32 + nf * 8 + (lane & 3) * 2;
            const float* c = acc[mt][nf];
            if (mode == 0) {
                float* p = Cf + coff;
                *(float2*)(p + row * ldc + col) = make_float2(c[0], c[1]);
                *(float2*)(p + (row + 8) * ldc + col) = make_float2(c[2], c[3]);
            } else if (mode == 3) {
                *(uint32_t*)(Chi + coff + row * ldc + col) = packh2(c[0], c[1]);
                *(uint32_t*)(Chi + coff + (row + 8) * ldc + col) = packh2(c[2], c[3]);
            } else {
                bool isV = (mode == 2) && (((col >> 7) & 1) == 0);
                if (isV) {   // K columns in kv mode -> fp16 single
                    *(uint32_t*)(Chi + coff + row * ldc + col) = packh2(c[0], c[1]);
                    *(uint32_t*)(Chi + coff + (row + 8) * ldc + col) = packh2(c[2], c[3]);
                } else {
                    uint32_t h0, l0, h1, l1;
                    split2(c[0], c[1], h0, l0);
                    split2(c[2], c[3], h1, l1);
                    *(uint32_t*)(Chi + coff + row * ldc + col) = h0;
                    *(uint32_t*)(Chi + coff + (row + 8) * ldc + col) = h1;
                    *(uint32_t*)(Clo + coff + row * ldc + col) = l0;
                    *(uint32_t*)(Clo + coff + (row + 8) * ldc + col) = l1;
                }
            }
        }
}

// =================================================================
// HMMA flash attention: BM=128, BN=64, 8 warps
// QK fp16 1-pass; PV split-bf16 3-pass. Q frags in registers.
// =================================================================
#define ROWB 272
#define QT   (128*ROWB)
#define KVT  (64*ROWB)
#define KV3  (3*KVT)
#define FA_SMEM (QT + 3*KV3)   // 191488
#define SCL 0.1275174313213403f  // 1/sqrt(128) * log2(e)
#define NIT (KL/64)

#define KVLOAD(stb, jb) do {                                                   \
    long long rg = ((long long)(bb*KL + (jb)*64 + kr)) * 4096 + hh*256 + kq*32; \
    uint32_t d = (stb) + kr * ROWB + kq * 64;                                  \
    _Pragma("unroll")                                                          \
    for (int _j = 0; _j < 4; _j++) {                                           \
        cpa16(d + _j*16,          KVh + rg + _j*8);                            \
        cpa16(d + KVT + _j*16,    KVh + rg + 128 + _j*8);                      \
        cpa16(d + 2*KVT + _j*16,  KVl + rg + 128 + _j*8);                      \
    }                                                                          \
} while (0)

__global__ __launch_bounds__(256, 1) void flash(
    const bf16* __restrict__ Qh,
    const bf16* __restrict__ KVh, const bf16* __restrict__ KVl,
    bf16* __restrict__ Ohi, bf16* __restrict__ Olo)
{
    extern __shared__ char smc[];
    const uint32_t sb = smem_u32(smc);
    const uint32_t kv0 = sb + QT;
    const int tid = threadIdx.x, lane = tid & 31, wid = tid >> 5;
    const int qt = blockIdx.x, hh = blockIdx.y, bb = blockIdx.z;
    const int kr = tid >> 2, kq = tid & 3;

    // Q (fp16 payload): 128 rows x 256B
    {
        int r = tid >> 1, hc = tid & 1;
        long long rg = ((long long)(bb*QL + qt*128 + r)) * 3072 + hh*192 + hc*64;
        uint32_t d = sb + r * ROWB + hc * 128;
#pragma unroll
        for (int j = 0; j < 8; j++) cpa16(d + j*16, Qh + rg + j*8);
    }
    CP_COMMIT();
    KVLOAD(kv0, 0);            CP_COMMIT();
    KVLOAD(kv0 + KV3, 1);      CP_COMMIT();

    float O[16][4];
#pragma unroll
    for (int i = 0; i < 16; i++)
#pragma unroll
        for (int j = 0; j < 4; j++) O[i][j] = 0.f;
    float m0v = -1e30f, m1v = -1e30f, l0v = 0.f, l1v = 0.f;

    const uint32_t a_q = sb + (wid * 16 + (lane & 15)) * ROWB + (lane >> 4) * 16;
    const uint32_t bk_rel = ((lane & 7) + ((lane >> 4) << 3)) * ROWB + ((lane >> 3) & 1) * 16;
    const uint32_t vt_rel = KVT + (lane & 15) * ROWB + ((lane >> 4) << 4);

    CP_WAIT2();
    __syncthreads();
    uint32_t qfh[8][4];
#pragma unroll
    for (int d16 = 0; d16 < 8; d16++) ldsm4(qfh[d16], a_q + d16 * 32);

#pragma unroll 1
    for (int jb = 0; jb < NIT; jb++) {
        const uint32_t stb = kv0 + (jb % 3) * KV3;
        if (jb + 1 < NIT) CP_WAIT1();
        else              CP_WAIT0();
        __syncthreads();
        if (jb + 2 < NIT) { KVLOAD(kv0 + ((jb + 2) % 3) * KV3, jb + 2); CP_COMMIT(); }

        // ---- S = Qh Kh^T (fp16 1-pass) ----
        float S[8][4];
#pragma unroll
        for (int f = 0; f < 8; f++)
#pragma unroll
            for (int e = 0; e < 4; e++) S[f][e] = 0.f;

        const uint32_t bk = stb + bk_rel;
#pragma unroll
        for (int d16 = 0; d16 < 8; d16++) {
#pragma unroll
            for (int np = 0; np < 4; np++) {
                uint32_t kh4[4];
                ldsm4(kh4, bk + np * (16 * ROWB) + d16 * 32);
                mmafp(S[np*2],   qfh[d16], kh4[0], kh4[1]);
                mmafp(S[np*2+1], qfh[d16], kh4[2], kh4[3]);
            }
        }

        // ---- online softmax ----
        float mloc0 = -1e30f, mloc1 = -1e30f;
#pragma unroll
        for (int f = 0; f < 8; f++) {
            S[f][0] *= SCL; S[f][1] *= SCL; S[f][2] *= SCL; S[f][3] *= SCL;
            mloc0 = fmaxf(mloc0, fmaxf(S[f][0], S[f][1]));
            mloc1 = fmaxf(mloc1, fmaxf(S[f][2], S[f][3]));
        }
        mloc0 = fmaxf(mloc0, __shfl_xor_sync(~0u, mloc0, 1));
        mloc0 = fmaxf(mloc0, __shfl_xor_sync(~0u, mloc0, 2));
        mloc1 = fmaxf(mloc1, __shfl_xor_sync(~0u, mloc1, 1));
        mloc1 = fmaxf(mloc1, __shfl_xor_sync(~0u, mloc1, 2));
        float mn0 = fmaxf(m0v, mloc0), mn1 = fmaxf(m1v, mloc1);
        float a0 = exp2f(m0v - mn0), a1 = exp2f(m1v - mn1);
        m0v = mn0; m1v = mn1;
        float sum0 = 0.f, sum1 = 0.f;
#pragma unroll
        for (int f = 0; f < 8; f++) {
            S[f][0] = exp2f(S[f][0] - mn0); S[f][1] = exp2f(S[f][1] - mn0);
            S[f][2] = exp2f(S[f][2] - mn1); S[f][3] = exp2f(S[f][3] - mn1);
            sum0 += S[f][0] + S[f][1];
            sum1 += S[f][2] + S[f][3];
        }
        sum0 += __shfl_xor_sync(~0u, sum0, 1); sum0 += __shfl_xor_sync(~0u, sum0, 2);
        sum1 += __shfl_xor_sync(~0u, sum1, 1); sum1 += __shfl_xor_sync(~0u, sum1, 2);
        l0v = l0v * a0 + sum0; l1v = l1v * a1 + sum1;
#pragma unroll
        for (int i = 0; i < 16; i++) {
            O[i][0] *= a0; O[i][1] *= a0; O[i][2] *= a1; O[i][3] *= a1;
        }

        // ---- O += P V (split-bf16 3-pass) ----
        const uint32_t vt = stb + vt_rel;
#pragma unroll
        for (int ks = 0; ks < 4; ks++) {
            uint32_t ph[4], pl[4];
            split2(S[2*ks][0],   S[2*ks][1],   ph[0], pl[0]);
            split2(S[2*ks][2],   S[2*ks][3],   ph[1], pl[1]);
            split2(S[2*ks+1][0], S[2*ks+1][1], ph[2], pl[2]);
            split2(S[2*ks+1][2], S[2*ks+1][3], ph[3], pl[3]);
#pragma unroll
            for (int dn = 0; dn < 8; dn++) {
                uint32_t vh[4], vl[4];
                ldsm4t(vh, vt + ks * (16 * ROWB) + dn * 32);
                ldsm4t(vl, vt + KVT + ks * (16 * ROWB) + dn * 32);
                mmabf(O[dn*2],   ph, vh[0], vh[1]);
                mmabf(O[dn*2],   ph, vl[0], vl[1]);
                mmabf(O[dn*2],   pl, vh[0], vh[1]);
                mmabf(O[dn*2+1], ph, vh[2], vh[3]);
                mmabf(O[dn*2+1], ph, vl[2], vl[3]);
                mmabf(O[dn*2+1], pl, vh[2], vh[3]);
            }
        }
    }

    // ---- epilogue ----
    float i0 = 1.f / l0v, i1 = 1.f / l1v;
    long long row0 = (long long)(bb*QL + qt*128 + wid*16 + (lane >> 2)) * 2048 + hh*128;
    int cc = (lane & 3) * 2;
#pragma unroll
    for (int nf = 0; nf < 16; nf++) {
        uint32_t h0, l0, h1, l1;
        split2(O[nf][0] * i0, O[nf][1] * i0, h0, l0);
        split2(O[nf][2] * i1, O[nf][3] * i1, h1, l1);
        long long c0 = row0 + nf*8 + cc;
        *(uint32_t*)(Ohi + c0) = h0;         *(uint32_t*)(Olo + c0) = l0;
        *(uint32_t*)(Ohi + c0 + 8*2048) = h1; *(uint32_t*)(Olo + c0 + 8*2048) = l1;
    }
}

// =================================================================
// launch (kv-down hgemm at launch index 3 for ncu capture)
// =================================================================
extern "C" void kernel_launch(void* const* d_in, const int* in_sizes, int n_in,
                              void* d_out, int out_size)
{
    const float* x_q       = (const float*)d_in[0];
    const float* x_kv      = (const float*)d_in[1];
    const float* W_dQ      = (const float*)d_in[2];
    const float* q_norm_w  = (const float*)d_in[3];
    const float* W_uQ      = (const float*)d_in[4];
    const float* W_dKV     = (const float*)d_in[5];
    const float* kv_norm_w = (const float*)d_in[6];
    const float* W_ukv     = (const float*)d_in[7];
    const float* W_o       = (const float*)d_in[8];
    float* out = (float*)d_out;

    float *qpart, *ckv;
    cudaGetSymbolAddress((void**)&qpart, g_qpart);
    cudaGetSymbolAddress((void**)&ckv,  g_ckv);
    bf16 *xqh,*xql,*xkvh,*xkvl,*qlh,*qll,*ckvh,*ckvl,*qh,*kvh,*kvl,*ath,*atl;
    bf16 *wdqh,*wdql,*wuqh,*wuql,*wdkvh,*wdkvl,*wukvh,*wukvl,*woh,*wol;
    cudaGetSymbolAddress((void**)&xqh,  s_xq_hi);   cudaGetSymbolAddress((void**)&xql,  s_xq_lo);
    cudaGetSymbolAddress((void**)&xkvh, s_xkv_hi);  cudaGetSymbolAddress((void**)&xkvl, s_xkv_lo);
    cudaGetSymbolAddress((void**)&qlh,  s_qlat_hi); cudaGetSymbolAddress((void**)&qll,  s_qlat_lo);
    cudaGetSymbolAddress((void**)&ckvh, s_ckv_hi);  cudaGetSymbolAddress((void**)&ckvl, s_ckv_lo);
    cudaGetSymbolAddress((void**)&qh,   s_q_hi);
    cudaGetSymbolAddress((void**)&kvh,  s_kv_hi);   cudaGetSymbolAddress((void**)&kvl,  s_kv_lo);
    cudaGetSymbolAddress((void**)&ath,  s_attn_hi); cudaGetSymbolAddress((void**)&atl,  s_attn_lo);
    cudaGetSymbolAddress((void**)&wdqh, w_dq_hi);   cudaGetSymbolAddress((void**)&wdql, w_dq_lo);
    cudaGetSymbolAddress((void**)&wuqh, w_uq_hi);   cudaGetSymbolAddress((void**)&wuql, w_uq_lo);
    cudaGetSymbolAddress((void**)&wdkvh, w_dkv_hi); cudaGetSymbolAddress((void**)&wdkvl, w_dkv_lo);
    cudaGetSymbolAddress((void**)&wukvh, w_ukv_hi); cudaGetSymbolAddress((void**)&wukvl, w_ukv_lo);
    cudaGetSymbolAddress((void**)&woh,  w_o_hi);    cudaGetSymbolAddress((void**)&wol,  w_o_lo);

    cudaFuncSetAttribute(hgemm, cudaFuncAttributeMaxDynamicSharedMemorySize, GEMM_SMEM);
    cudaFuncSetAttribute(flash, cudaFuncAttributeMaxDynamicSharedMemorySize, FA_SMEM);

    dim3 tb(32, 8);
    // 0-2: prep for kv-down
    split_kernel<<<4096, 256>>>(x_kv, xkvh, xkvl, (long long)BKL*HID/4);
    splitT_kernel<<<dim3(1024/32, HID/32), tb>>>(W_dKV, wdkvh, wdkvl, 1088, HID, 0, 0);
    split_kernel<<<2048, 256>>>(x_q,  xqh,  xql,  (long long)BQL*HID/4);

    // 3: ckv = (x_kv @ W_dKV)[:, :1024]  (ncu target)
    hgemm<<<dim3(8, 64), 256, GEMM_SMEM>>>(xkvh, xkvl, HID, wdkvh, wdkvl, HID,
                                           ckv, nullptr, nullptr, GG*LAT, HID, 0, 0, 0, 0);
    // 4: rmsnorm per group + split
    rmsnorm_split<<<dim3(BKL, GG), 256>>>(ckv, kv_norm_w, ckvh, ckvl, LAT, GG*LAT, LAT, 1, 0);
    // 5: W_ukv transpose-split
    splitT_kernel<<<dim3(1024/32, LAT/32, GG), tb>>>(W_ukv, wukvh, wukvl, 1024, LAT,
                                                     (long long)LAT*1024, (long long)1024*LAT);
    // 6: kv[g] = ckv_g @ W_ukv[g]^T  (K cols fp16, V cols bf16 hi/lo)
    hgemm<<<dim3(8, 64, GG), 256, GEMM_SMEM>>>(ckvh, ckvl, GG*LAT, wukvh, wukvl, LAT,
                                               nullptr, kvh, kvl, 4096, LAT,
                                               (long long)LAT, (long long)1024*LAT, (long long)1024, 2);
    // 7: W_dQ transpose-split
    splitT_kernel<<<dim3(QLR/32, HID/32), tb>>>(W_dQ, wdqh, wdql, QLR, HID, 0, 0);
    // 8: q_lat partials, split-K=4
    hgemm<<<dim3(4, 16, 4), 256, GEMM_SMEM>>>(xqh, xql, HID, wdqh, wdql, HID,
                                              qpart, nullptr, nullptr, QLR, 512,
                                              512, 512, (long long)BQL*QLR, 0);
    // 9: reduce + rmsnorm + split
    rmsnorm_split<<<dim3(BQL, 1), 256>>>(qpart, q_norm_w, qlh, qll, QLR, QLR, QLR,
                                         4, (long long)BQL*QLR);
    // 10: W_uQ transpose-split
    splitT_kernel<<<dim3(3072/32, QLR/32), tb>>>(W_uQ, wuqh, wuql, 3072, QLR, 0, 0);
    // 11: q = q_lat @ W_uQ  (fp16 out)
    hgemm<<<dim3(24, 16), 256, GEMM_SMEM>>>(qlh, qll, QLR, wuqh, wuql, QLR,
                                            nullptr, qh, nullptr, 3072, QLR, 0, 0, 0, 3);
    // 12: flash attention
    flash<<<dim3(QL/128, HH, BB), 256, FA_SMEM>>>(qh, kvh, kvl, ath, atl);
    // 13: W_o transpose-split
    splitT_kernel<<<dim3(HID/32, 2048/32), tb>>>(W_o, woh, wol, HID, 2048, 0, 0);
    // 14: out = attn @ W_o
    hgemm<<<dim3(16, 16), 256, GEMM_SMEM>>>(ath, atl, 2048, woh, wol, HID,
                                            out, nullptr, nullptr, HID, 2048, 0, 0, 0, 0);
}

// round 9
// speedup vs baseline: 6.5111x; 1.8920x over previous
#include <cuda_runtime.h>
#include <cuda_bf16.h>
#include <cuda_fp16.h>
#include <stdint.h>

#define BB 2
#define QL 1024
#define KL 4096
#define HID 2048
#define HH 16
#define HD 128
#define GG 4
#define QLR 512
#define LAT 256
#define BQL (BB*QL)
#define BKL (BB*KL)

__device__ float g_qpart[4 * BQL * QLR];
__device__ float g_ckv [BKL * (GG*LAT)];

__device__ __half h_xq  [BQL*HID];
__device__ __half h_xkv [BKL*HID];
__device__ __half h_qlat[BQL*QLR];
__device__ __half h_ckv [BKL*GG*LAT];
__device__ __half h_q   [BQL*3072];
__device__ __half h_kv  [(long long)BKL*4096];
__device__ __half h_attn[BQL*2048];
__device__ __half hw_dq [QLR*HID];
__device__ __half hw_uq [3072*QLR];
__device__ __half hw_dkv[1024*HID];
__device__ __half hw_ukv[GG*1024*LAT];
__device__ __half hw_o  [HID*2048];

__device__ __forceinline__ uint32_t smem_u32(const void* p) {
    uint32_t a;
    asm("{ .reg .u64 t; cvta.to.shared.u64 t, %1; cvt.u32.u64 %0, t; }" : "=r"(a) : "l"(p));
    return a;
}
__device__ __forceinline__ void cpa16(uint32_t dst, const void* src) {
    asm volatile("cp.async.cg.shared.global [%0], [%1], 16;" :: "r"(dst), "l"(src));
}
#define CP_COMMIT() asm volatile("cp.async.commit_group;")
#define CP_WAIT0()  asm volatile("cp.async.wait_group 0;")
#define CP_WAIT1()  asm volatile("cp.async.wait_group 1;")
#define CP_WAIT2()  asm volatile("cp.async.wait_group 2;")

__device__ __forceinline__ void ldsm4(uint32_t* r, uint32_t a) {
    asm volatile("ldmatrix.sync.aligned.m8n8.x4.shared.b16 {%0,%1,%2,%3}, [%4];"
        : "=r"(r[0]), "=r"(r[1]), "=r"(r[2]), "=r"(r[3]) : "r"(a));
}
__device__ __forceinline__ void ldsm4t(uint32_t* r, uint32_t a) {
    asm volatile("ldmatrix.sync.aligned.m8n8.x4.trans.shared.b16 {%0,%1,%2,%3}, [%4];"
        : "=r"(r[0]), "=r"(r[1]), "=r"(r[2]), "=r"(r[3]) : "r"(a));
}
__device__ __forceinline__ void mmafp(float* c, const uint32_t* a, uint32_t b0, uint32_t b1) {
    asm volatile(
        "mma.sync.aligned.m16n8k16.row.col.f32.f16.f16.f32 "
        "{%0,%1,%2,%3}, {%4,%5,%6,%7}, {%8,%9}, {%0,%1,%2,%3};"
        : "+f"(c[0]), "+f"(c[1]), "+f"(c[2]), "+f"(c[3])
        : "r"(a[0]), "r"(a[1]), "r"(a[2]), "r"(a[3]), "r"(b0), "r"(b1));
}
__device__ __forceinline__ uint32_t packh2(float a, float b) {
    __half2 h = __floats2half2_rn(a, b);
    return *reinterpret_cast<uint32_t*>(&h);
}

// ---------------- fp32 -> fp16 convert ----------------
__global__ void conv_kernel(const float* __restrict__ A, __half* __restrict__ o, long long n4)
{
    long long i = blockIdx.x * (long long)blockDim.x + threadIdx.x;
    long long st = (long long)gridDim.x * blockDim.x;
    for (; i < n4; i += st) {
        float4 v = ((const float4*)A)[i];
        ((uint32_t*)o)[2*i]   = packh2(v.x, v.y);
        ((uint32_t*)o)[2*i+1] = packh2(v.z, v.w);
    }
}

// B [K,N] (ldb) -> oT [N,K] (ldt), fp16, z-batched
__global__ void convT_kernel(const float* __restrict__ B, __half* __restrict__ oT,
                             int ldb, int ldt, long long sB, long long sO)
{
    B += blockIdx.z * sB; oT += blockIdx.z * sO;
    __shared__ float t[32][33];
    int tx = threadIdx.x, ty = threadIdx.y;
    int n0 = blockIdx.x * 32, k0 = blockIdx.y * 32;
#pragma unroll
    for (int j = ty; j < 32; j += 8)
        t[j][tx] = B[(long long)(k0 + j) * ldb + n0 + tx];
    __syncthreads();
#pragma unroll
    for (int j = ty; j < 32; j += 8)
        oT[(long long)(n0 + j) * ldt + k0 + tx] = __float2half_rn(t[tx][j]);
}

// ---------------- rmsnorm + convert (split-K reduction) ----------------
__global__ void rmsnorm_conv(const float* __restrict__ x, const float* __restrict__ w,
                             __half* __restrict__ o, int n, int rowStride, int segStride,
                             int nsplit, long long splitStride)
{
    long long off = (long long)blockIdx.x * rowStride + (long long)blockIdx.y * segStride;
    const float* wp = w + (long long)blockIdx.y * n;
    __shared__ float buf[512];
    __shared__ float red[8]; __shared__ float rs;
    float s = 0.f;
    for (int i = threadIdx.x; i < n; i += 256) {
        float v = 0.f;
        for (int k = 0; k < nsplit; k++) v += x[(long long)k * splitStride + off + i];
        buf[i] = v;
        s += v * v;
    }
#pragma unroll
    for (int oo = 16; oo; oo >>= 1) s += __shfl_xor_sync(~0u, s, oo);
    if ((threadIdx.x & 31) == 0) red[threadIdx.x >> 5] = s;
    __syncthreads();
    if (threadIdx.x == 0) {
        float t = 0.f;
#pragma unroll
        for (int i = 0; i < 8; i++) t += red[i];
        rs = rsqrtf(t / (float)n + 1e-6f);
    }
    __syncthreads();
    float r = rs;
    for (int i = threadIdx.x; i < n; i += 256)
        o[off + i] = __float2half_rn(buf[i] * r * wp[i]);
}

// =================================================================
// fp16 1-pass HMMA GEMM: C[M,N] = A[M,K] * B[N,K]^T
// 128x128 tile, BK=32, 8 warps (2x4), XOR-swizzled 64B rows,
// 4-stage cp.async pipeline, 2 CTAs/SM. mode: 0=fp32 out, 1=fp16 out
// =================================================================
#define GT   8192            // one 128x32 fp16 tile (64B rows)
#define GSTG (2*GT)          // A | B
#define GEMM_SMEM (4*GSTG)   // 65536

#define GLOAD(stg, k0) do {                                         \
    _Pragma("unroll")                                               \
    for (int _j = 0; _j < 2; _j++) {                                \
        int _c = lc * 2 + _j;                                       \
        uint32_t _d = (stg) + soff[_j];                             \
        cpa16(_d,        gA + (k0) + _c * 8);                       \
        cpa16(_d + GT,   gB + (k0) + _c * 8);                       \
    }                                                               \
} while (0)

__global__ __launch_bounds__(256, 2) void hgemm16(
    const __half* __restrict__ A, int lda,
    const __half* __restrict__ B, int ldb,
    float* Cf, __half* Ch, int ldc, int K,
    long long sAz, long long sBz, long long sCz, int mode)
{
    extern __shared__ char smc[];
    const uint32_t sb = smem_u32(smc);
    const int tid = threadIdx.x, lane = tid & 31, wid = tid >> 5;
    const int m0 = blockIdx.y * 128, n0 = blockIdx.x * 128;
    const int wm = wid >> 2, wn = wid & 3;

    A += blockIdx.z * sAz;  B += blockIdx.z * sBz;
    long long coff = blockIdx.z * sCz;

    const int lrow = tid >> 1, lc = tid & 1;
    const int lsw = (lrow >> 1) & 3;
    const __half* gA = A + (long long)(m0 + lrow) * lda;
    const __half* gB = B + (long long)(n0 + lrow) * ldb;
    uint32_t soff[2];
    soff[0] = lrow * 64 + (((lc * 2 + 0) ^ lsw) * 16);
    soff[1] = lrow * 64 + (((lc * 2 + 1) ^ lsw) * 16);

    float acc[4][4][4];
#pragma unroll
    for (int i = 0; i < 4; i++)
#pragma unroll
        for (int j = 0; j < 4; j++)
#pragma unroll
            for (int k = 0; k < 4; k++) acc[i][j][k] = 0.f;

    const int rlA = lane & 15, swA = (rlA >> 1) & 3, cAhi = lane >> 4;
    const uint32_t aRel = (wm * 64 + rlA) * 64;
    uint32_t aOff[2] = { (uint32_t)(((0 + cAhi) ^ swA) * 16),
                         (uint32_t)(((2 + cAhi) ^ swA) * 16) };
    const int rlB = (lane & 7) | ((lane >> 4) << 3), swB = (rlB >> 1) & 3, cB = (lane >> 3) & 1;
    const uint32_t bRel = GT + (wn * 32 + rlB) * 64;
    uint32_t bOff[2] = { (uint32_t)(((0 + cB) ^ swB) * 16),
                         (uint32_t)(((2 + cB) ^ swB) * 16) };

    const int nIter = K >> 5;
    GLOAD(sb, 0);             CP_COMMIT();
    GLOAD(sb + GSTG, 32);     CP_COMMIT();
    GLOAD(sb + 2*GSTG, 64);   CP_COMMIT();

#pragma unroll 1
    for (int it = 0; it < nIter; it++) {
        if (it + 2 < nIter)      CP_WAIT2();
        else if (it + 1 < nIter) CP_WAIT1();
        else                     CP_WAIT0();
        __syncthreads();
        if (it + 3 < nIter) { GLOAD(sb + ((it + 3) & 3) * GSTG, (it + 3) << 5); CP_COMMIT(); }

        const uint32_t stg = sb + (it & 3) * GSTG;
#pragma unroll
        for (int s2 = 0; s2 < 2; s2++) {
            uint32_t ah[4][4], bh[4][2];
#pragma unroll
            for (int mt = 0; mt < 4; mt++)
                ldsm4(ah[mt], stg + aRel + mt * 1024 + aOff[s2]);
#pragma unroll
            for (int np = 0; np < 2; np++) {
                uint32_t t[4];
                ldsm4(t, stg + bRel + np * 1024 + bOff[s2]);
                bh[np*2][0] = t[0]; bh[np*2][1] = t[1];
                bh[np*2+1][0] = t[2]; bh[np*2+1][1] = t[3];
            }
#pragma unroll
            for (int mt = 0; mt < 4; mt++)
#pragma unroll
                for (int nf = 0; nf < 4; nf++)
                    mmafp(acc[mt][nf], ah[mt], bh[nf][0], bh[nf][1]);
        }
    }

#pragma unroll
    for (int mt = 0; mt < 4; mt++)
#pragma unroll
        for (int nf = 0; nf < 4; nf++) {
            long long row = m0 + wm * 64 + mt * 16 + (lane >> 2);
            int col = n0 + wn * 32 + nf * 8 + (lane & 3) * 2;
            const float* c = acc[mt][nf];
            if (mode == 0) {
                float* p = Cf + coff;
                *(float2*)(p + row * ldc + col) = make_float2(c[0], c[1]);
                *(float2*)(p + (row + 8) * ldc + col) = make_float2(c[2], c[3]);
            } else {
                *(uint32_t*)(Ch + coff + row * ldc + col) = packh2(c[0], c[1]);
                *(uint32_t*)(Ch + coff + (row + 8) * ldc + col) = packh2(c[2], c[3]);
            }
        }
}

// =================================================================
// fp16 HMMA flash attention: BM=128, BN=64, 8 warps, all 1-pass
// smem: Q [128x272B] + 3 stages of {K, V} [64x272B each]
// =================================================================
#define ROWB 272
#define QT   (128*ROWB)
#define KVT  (64*ROWB)
#define KV2  (2*KVT)
#define FA_SMEM (QT + 3*KV2)   // 139264
#define SCL 0.1275174313213403f  // 1/sqrt(128) * log2(e)
#define NIT (KL/64)

#define KVLOAD(stb, jb) do {                                                   \
    long long rg = ((long long)(bb*KL + (jb)*64 + kr)) * 4096 + hh*256 + kq*32; \
    uint32_t d = (stb) + kr * ROWB + kq * 64;                                  \
    _Pragma("unroll")                                                          \
    for (int _j = 0; _j < 4; _j++) {                                           \
        cpa16(d + _j*16,        KVg + rg + _j*8);                              \
        cpa16(d + KVT + _j*16,  KVg + rg + 128 + _j*8);                        \
    }                                                                          \
} while (0)

__global__ __launch_bounds__(256, 1) void flash16(
    const __half* __restrict__ Qg,
    const __half* __restrict__ KVg,
    __half* __restrict__ Og)
{
    extern __shared__ char smc[];
    const uint32_t sb = smem_u32(smc);
    const uint32_t kv0 = sb + QT;
    const int tid = threadIdx.x, lane = tid & 31, wid = tid >> 5;
    const int qt = blockIdx.x, hh = blockIdx.y, bb = blockIdx.z;
    const int kr = tid >> 2, kq = tid & 3;

    // Q: 128 rows x 256B
    {
        int r = tid >> 1, hc = tid & 1;
        long long rg = ((long long)(bb*QL + qt*128 + r)) * 3072 + hh*192 + hc*64;
        uint32_t d = sb + r * ROWB + hc * 128;
#pragma unroll
        for (int j = 0; j < 8; j++) cpa16(d + j*16, Qg + rg + j*8);
    }
    CP_COMMIT();
    KVLOAD(kv0, 0);            CP_COMMIT();
    KVLOAD(kv0 + KV2, 1);      CP_COMMIT();

    float O[16][4];
#pragma unroll
    for (int i = 0; i < 16; i++)
#pragma unroll
        for (int j = 0; j < 4; j++) O[i][j] = 0.f;
    float m0v = -1e30f, m1v = -1e30f, l0v = 0.f, l1v = 0.f;

    const uint32_t a_q = sb + (wid * 16 + (lane & 15)) * ROWB + (lane >> 4) * 16;
    const uint32_t bk_rel = ((lane & 7) + ((lane >> 4) << 3)) * ROWB + ((lane >> 3) & 1) * 16;
    const uint32_t vt_rel = KVT + (lane & 15) * ROWB + ((lane >> 4) << 4);

    CP_WAIT2();
    __syncthreads();
    uint32_t qf[8][4];
#pragma unroll
    for (int d16 = 0; d16 < 8; d16++) ldsm4(qf[d16], a_q + d16 * 32);

#pragma unroll 1
    for (int jb = 0; jb < NIT; jb++) {
        const uint32_t stb = kv0 + (jb % 3) * KV2;
        if (jb + 1 < NIT) CP_WAIT1();
        else              CP_WAIT0();
        __syncthreads();
        if (jb + 2 < NIT) { KVLOAD(kv0 + ((jb + 2) % 3) * KV2, jb + 2); CP_COMMIT(); }

        // ---- S = Q K^T (fp16 1-pass) ----
        float S[8][4];
#pragma unroll
        for (int f = 0; f < 8; f++)
#pragma unroll
            for (int e = 0; e < 4; e++) S[f][e] = 0.f;

        const uint32_t bk = stb + bk_rel;
#pragma unroll
        for (int d16 = 0; d16 < 8; d16++) {
#pragma unroll
            for (int np = 0; np < 4; np++) {
                uint32_t kh4[4];
                ldsm4(kh4, bk + np * (16 * ROWB) + d16 * 32);
                mmafp(S[np*2],   qf[d16], kh4[0], kh4[1]);
                mmafp(S[np*2+1], qf[d16], kh4[2], kh4[3]);
            }
        }

        // ---- online softmax ----
        float mloc0 = -1e30f, mloc1 = -1e30f;
#pragma unroll
        for (int f = 0; f < 8; f++) {
            S[f][0] *= SCL; S[f][1] *= SCL; S[f][2] *= SCL; S[f][3] *= SCL;
            mloc0 = fmaxf(mloc0, fmaxf(S[f][0], S[f][1]));
            mloc1 = fmaxf(mloc1, fmaxf(S[f][2], S[f][3]));
        }
        mloc0 = fmaxf(mloc0, __shfl_xor_sync(~0u, mloc0, 1));
        mloc0 = fmaxf(mloc0, __shfl_xor_sync(~0u, mloc0, 2));
        mloc1 = fmaxf(mloc1, __shfl_xor_sync(~0u, mloc1, 1));
        mloc1 = fmaxf(mloc1, __shfl_xor_sync(~0u, mloc1, 2));
        float mn0 = fmaxf(m0v, mloc0), mn1 = fmaxf(m1v, mloc1);
        float a0 = exp2f(m0v - mn0), a1 = exp2f(m1v - mn1);
        m0v = mn0; m1v = mn1;
        float sum0 = 0.f, sum1 = 0.f;
#pragma unroll
        for (int f = 0; f < 8; f++) {
            S[f][0] = exp2f(S[f][0] - mn0); S[f][1] = exp2f(S[f][1] - mn0);
            S[f][2] = exp2f(S[f][2] - mn1); S[f][3] = exp2f(S[f][3] - mn1);
            sum0 += S[f][0] + S[f][1];
            sum1 += S[f][2] + S[f][3];
        }
        sum0 += __shfl_xor_sync(~0u, sum0, 1); sum0 += __shfl_xor_sync(~0u, sum0, 2);
        sum1 += __shfl_xor_sync(~0u, sum1, 1); sum1 += __shfl_xor_sync(~0u, sum1, 2);
        l0v = l0v * a0 + sum0; l1v = l1v * a1 + sum1;
#pragma unroll
        for (int i = 0; i < 16; i++) {
            O[i][0] *= a0; O[i][1] *= a0; O[i][2] *= a1; O[i][3] *= a1;
        }

        // ---- O += P V (fp16 1-pass) ----
        const uint32_t vt = stb + vt_rel;
#pragma unroll
        for (int ks = 0; ks < 4; ks++) {
            uint32_t ph[4];
            ph[0] = packh2(S[2*ks][0],   S[2*ks][1]);
            ph[1] = packh2(S[2*ks][2],   S[2*ks][3]);
            ph[2] = packh2(S[2*ks+1][0], S[2*ks+1][1]);
            ph[3] = packh2(S[2*ks+1][2], S[2*ks+1][3]);
#pragma unroll
            for (int dn = 0; dn < 8; dn++) {
                uint32_t vh[4];
                ldsm4t(vh, vt + ks * (16 * ROWB) + dn * 32);
                mmafp(O[dn*2],   ph, vh[0], vh[1]);
                mmafp(O[dn*2+1], ph, vh[2], vh[3]);
            }
        }
    }

    // ---- epilogue: fp16 attn out ----
    float i0 = 1.f / l0v, i1 = 1.f / l1v;
    long long row0 = (long long)(bb*QL + qt*128 + wid*16 + (lane >> 2)) * 2048 + hh*128;
    int cc = (lane & 3) * 2;
#pragma unroll
    for (int nf = 0; nf < 16; nf++) {
        long long c0 = row0 + nf*8 + cc;
        *(uint32_t*)(Og + c0)          = packh2(O[nf][0] * i0, O[nf][1] * i0);
        *(uint32_t*)(Og + c0 + 8*2048) = packh2(O[nf][2] * i1, O[nf][3] * i1);
    }
}

// =================================================================
// launch (kv-down hgemm16 at index 3 for ncu capture)
// =================================================================
extern "C" void kernel_launch(void* const* d_in, const int* in_sizes, int n_in,
                              void* d_out, int out_size)
{
    const float* x_q       = (const float*)d_in[0];
    const float* x_kv      = (const float*)d_in[1];
    const float* W_dQ      = (const float*)d_in[2];
    const float* q_norm_w  = (const float*)d_in[3];
    const float* W_uQ      = (const float*)d_in[4];
    const float* W_dKV     = (const float*)d_in[5];
    const float* kv_norm_w = (const float*)d_in[6];
    const float* W_ukv     = (const float*)d_in[7];
    const float* W_o       = (const float*)d_in[8];
    float* out = (float*)d_out;

    float *qpart, *ckv;
    cudaGetSymbolAddress((void**)&qpart, g_qpart);
    cudaGetSymbolAddress((void**)&ckv,  g_ckv);
    __half *xq, *xkv, *qlat, *ckvh, *q, *kv, *attn;
    __half *wdq, *wuq, *wdkv, *wukv, *wo;
    cudaGetSymbolAddress((void**)&xq,   h_xq);
    cudaGetSymbolAddress((void**)&xkv,  h_xkv);
    cudaGetSymbolAddress((void**)&qlat, h_qlat);
    cudaGetSymbolAddress((void**)&ckvh, h_ckv);
    cudaGetSymbolAddress((void**)&q,    h_q);
    cudaGetSymbolAddress((void**)&kv,   h_kv);
    cudaGetSymbolAddress((void**)&attn, h_attn);
    cudaGetSymbolAddress((void**)&wdq,  hw_dq);
    cudaGetSymbolAddress((void**)&wuq,  hw_uq);
    cudaGetSymbolAddress((void**)&wdkv, hw_dkv);
    cudaGetSymbolAddress((void**)&wukv, hw_ukv);
    cudaGetSymbolAddress((void**)&wo,   hw_o);

    cudaFuncSetAttribute(hgemm16, cudaFuncAttributeMaxDynamicSharedMemorySize, GEMM_SMEM);
    cudaFuncSetAttribute(flash16, cudaFuncAttributeMaxDynamicSharedMemorySize, FA_SMEM);

    dim3 tb(32, 8);
    // 0-2: prep for kv-down
    conv_kernel<<<4096, 256>>>(x_kv, xkv, (long long)BKL*HID/4);
    convT_kernel<<<dim3(1024/32, HID/32), tb>>>(W_dKV, wdkv, 1088, HID, 0, 0);
    conv_kernel<<<2048, 256>>>(x_q, xq, (long long)BQL*HID/4);

    // 3: ckv = (x_kv @ W_dKV)[:, :1024]  (ncu target)
    hgemm16<<<dim3(8, 64), 256, GEMM_SMEM>>>(xkv, HID, wdkv, HID,
                                             ckv, nullptr, GG*LAT, HID, 0, 0, 0, 0);
    // 4: rmsnorm per group + convert
    rmsnorm_conv<<<dim3(BKL, GG), 256>>>(ckv, kv_norm_w, ckvh, LAT, GG*LAT, LAT, 1, 0);
    // 5: W_ukv transpose-convert
    convT_kernel<<<dim3(1024/32, LAT/32, GG), tb>>>(W_ukv, wukv, 1024, LAT,
                                                    (long long)LAT*1024, (long long)1024*LAT);
    // 6: kv[g] = ckv_g @ W_ukv[g]^T  -> fp16
    hgemm16<<<dim3(8, 64, GG), 256, GEMM_SMEM>>>(ckvh, GG*LAT, wukv, LAT,
                                                 nullptr, kv, 4096, LAT,
                                                 (long long)LAT, (long long)1024*LAT, (long long)1024, 1);
    // 7: W_dQ transpose-convert
    convT_kernel<<<dim3(QLR/32, HID/32), tb>>>(W_dQ, wdq, QLR, HID, 0, 0);
    // 8: q_lat partials, split-K=4
    hgemm16<<<dim3(4, 16, 4), 256, GEMM_SMEM>>>(xq, HID, wdq, HID,
                                                qpart, nullptr, QLR, 512,
                                                512, 512, (long long)BQL*QLR, 0);
    // 9: reduce + rmsnorm + convert
    rmsnorm_conv<<<dim3(BQL, 1), 256>>>(qpart, q_norm_w, qlat, QLR, QLR, QLR,
                                        4, (long long)BQL*QLR);
    // 10: W_uQ transpose-convert
    convT_kernel<<<dim3(3072/32, QLR/32), tb>>>(W_uQ, wuq, 3072, QLR, 0, 0);
    // 11: q = q_lat @ W_uQ  -> fp16
    hgemm16<<<dim3(24, 16), 256, GEMM_SMEM>>>(qlat, QLR, wuq, QLR,
                                              nullptr, q, 3072, QLR, 0, 0, 0, 1);
    // 12: flash attention -> fp16 attn
    flash16<<<dim3(QL/128, HH, BB), 256, FA_SMEM>>>(q, kv, attn);
    // 13: W_o transpose-convert
    convT_kernel<<<dim3(HID/32, 2048/32), tb>>>(W_o, wo, HID, 2048, 0, 0);
    // 14: out = attn @ W_o -> fp32
    hgemm16<<<dim3(16, 16), 256, GEMM_SMEM>>>(attn, 2048, wo, HID,
                                              out, nullptr, HID, 2048, 0, 0, 0, 0);
}